// round 14
// baseline (speedup 1.0000x reference)
#include <cuda_runtime.h>
#include <cuda_fp16.h>
#include <cstdint>
#include <cstdio>
#include <cstdlib>
#include <cstring>
#include <dlfcn.h>

#define Dd 768
#define Cc 256
#define BLn 1024
#define HD (Dd * Dd)          // 589824
#define BLD (BLn * Dd)        // 786432
#define BLC (BLn * Cc)        // 262144

// Scratch (device globals: allocation-free rule; zero-initialized)
__device__ __half g_Xh[BLD];
__device__ __half g_w13h[2 * HD];                 // sw1 || ew1
__device__ __half g_w24h[2 * HD];                 // sw2 || ew2
__device__ __half g_W2h[Cc * 2 * Dd];
__device__ __half g_W1th[(size_t)Cc * Dd * Dd];   // [c][e][d] half
__device__ __half g_Htmp2[2 * BLD];               // s-hidden || e-hidden
__device__ __half g_HsHe[2 * BLD];                // Hs || He  (2048 x 768)
__device__ __half g_Th[(size_t)BLn * Cc * Dd];    // T[bi][c][e] half
__device__ float  g_LsLe[2 * BLC];                // Ls || Le
__device__ float  g_b1x[2 * Dd];                  // sb1 || eb1
__device__ float  g_b2x[2 * Dd];                  // sb2 || eb2
__device__ int    g_bad;
__device__ __align__(128) unsigned char g_tmaps[8 * 128];   // CUtensorMaps

static __device__ __forceinline__ uint32_t smem_u32(const void* p) {
    uint32_t a;
    asm("{ .reg .u64 t; cvta.to.shared.u64 t, %1; cvt.u32.u64 %0, t; }" : "=r"(a) : "l"(p));
    return a;
}
static __device__ __forceinline__ void cp16(uint32_t dst, const void* src) {
    asm volatile("cp.async.cg.shared.global [%0], [%1], 16;" :: "r"(dst), "l"(src) : "memory");
}
static __device__ __forceinline__ void cp_commit() {
    asm volatile("cp.async.commit_group;" ::: "memory");
}
template <int N>
static __device__ __forceinline__ void cp_wait() {
    asm volatile("cp.async.wait_group %0;" :: "n"(N) : "memory");
}
static __device__ __forceinline__ void mma_f16(float& c0, float& c1, float& c2, float& c3,
                                               uint32_t a0, uint32_t a1, uint32_t a2, uint32_t a3,
                                               uint32_t b0, uint32_t b1) {
    asm volatile(
        "mma.sync.aligned.m16n8k16.row.col.f32.f16.f16.f32 "
        "{%0,%1,%2,%3}, {%4,%5,%6,%7}, {%8,%9}, {%0,%1,%2,%3};"
        : "+f"(c0), "+f"(c1), "+f"(c2), "+f"(c3)
        : "r"(a0), "r"(a1), "r"(a2), "r"(a3), "r"(b0), "r"(b1));
}

// ---------------------------------------------------------------------------
// Legacy fp16 mma.sync GEMM (fallback + validation reference; ~2022us path)
// ---------------------------------------------------------------------------
#define ROWH 72
#define ASTG (128 * ROWH)
#define SMEM_BYTES (4 * ASTG * 2 * 2 / 2)  // 73728

__global__ void __launch_bounds__(256, 2)
gemm_h(const __half* A, long saz, int lda,
       const __half* B, long sbz, int ldb,
       void* Cv, long scz, long ldc,
       int mode, const float* __restrict__ b1,
       const float* __restrict__ Lsg, const float* __restrict__ Leg,
       const float* __restrict__ W2bg, const float* __restrict__ biasg)
{
    extern __shared__ __half smh[];
    __half* As = smh;
    __half* Bs = smh + 2 * ASTG;
    const uint32_t sbase = smem_u32(smh);
    const uint32_t bbase = sbase + 2 * ASTG * 2;

    const int tid = threadIdx.x;
    const int z = blockIdx.z;
    float* Cf = (float*)Cv;
    __half* Ch = (__half*)Cv;
    if (mode == 4) {
        A += (long)(z >> 9) * 512 * Dd;
        B += (long)z * Cc * Dd;
        Cf += (long)z * 512 * Cc;
    } else {
        A += z * saz; B += z * sbz;
        Cf += z * scz; Ch += z * scz;
    }
    const int m0 = blockIdx.y * 128, n0 = blockIdx.x * 128;

    const int pr = tid >> 3, pc = tid & 7;
    const __half* pa0 = A + (long)(m0 + pr) * lda + pc * 8;
    const __half* pb0 = B + (long)(n0 + pr) * ldb + pc * 8;
    const uint32_t qoff = (uint32_t)(pr * ROWH * 2 + pc * 16);
    const uint32_t qa0 = sbase + qoff;
    const uint32_t qb0 = bbase + qoff;
    const uint32_t stgb = ASTG * 2;

    float acc[4][4][4];
#pragma unroll
    for (int mi = 0; mi < 4; mi++)
#pragma unroll
        for (int ni = 0; ni < 4; ni++)
#pragma unroll
            for (int r = 0; r < 4; r++) acc[mi][ni][r] = 0.f;

    const int lane = tid & 31, w = tid >> 5;
    const int g = lane >> 2, tig = lane & 3;
    const int wm = w & 1, wn = w >> 1;

#pragma unroll
    for (int i = 0; i < 4; i++) {
        cp16(qa0 + i * (32 * ROWH * 2), pa0 + (long)(32 * i) * lda);
        cp16(qb0 + i * (32 * ROWH * 2), pb0 + (long)(32 * i) * ldb);
    }
    cp_commit();

    for (int k0 = 0; k0 < 12; k0++) {
        cp_wait<0>();
        __syncthreads();
        if (k0 + 1 < 12) {
            const uint32_t so = ((k0 + 1) & 1) * stgb;
            const long go = (long)(k0 + 1) * 64;
#pragma unroll
            for (int i = 0; i < 4; i++) {
                cp16(qa0 + so + i * (32 * ROWH * 2), pa0 + (long)(32 * i) * lda + go);
                cp16(qb0 + so + i * (32 * ROWH * 2), pb0 + (long)(32 * i) * ldb + go);
            }
            cp_commit();
        }

        const __half* aw = As + (k0 & 1) * ASTG + (wm * 64) * ROWH;
        const __half* bw = Bs + (k0 & 1) * ASTG + (wn * 32) * ROWH;

#pragma unroll
        for (int ks = 0; ks < 4; ks++) {
            const int kh = ks * 16 + 2 * tig;
            uint32_t af[4][4], bf[4][2];
#pragma unroll
            for (int mi = 0; mi < 4; mi++) {
                const __half* p = aw + (mi * 16 + g) * ROWH + kh;
                af[mi][0] = *(const uint32_t*)(p);
                af[mi][1] = *(const uint32_t*)(p + 8 * ROWH);
                af[mi][2] = *(const uint32_t*)(p + 8);
                af[mi][3] = *(const uint32_t*)(p + 8 * ROWH + 8);
            }
#pragma unroll
            for (int ni = 0; ni < 4; ni++) {
                const __half* p = bw + (ni * 8 + g) * ROWH + kh;
                bf[ni][0] = *(const uint32_t*)(p);
                bf[ni][1] = *(const uint32_t*)(p + 8);
            }
#pragma unroll
            for (int mi = 0; mi < 4; mi++)
#pragma unroll
                for (int ni = 0; ni < 4; ni++)
                    mma_f16(acc[mi][ni][0], acc[mi][ni][1], acc[mi][ni][2], acc[mi][ni][3],
                            af[mi][0], af[mi][1], af[mi][2], af[mi][3],
                            bf[ni][0], bf[ni][1]);
        }
    }

    const float* lsr = nullptr; const float* leb = nullptr;
    if (mode == 4) {
        lsr = Lsg + (long)z * Cc;
        leb = Leg + (long)(z >> 9) * 512 * Cc;
    }
#pragma unroll
    for (int mi = 0; mi < 4; mi++) {
#pragma unroll
        for (int ni = 0; ni < 4; ni++) {
            const int col = n0 + wn * 32 + ni * 8 + tig * 2;
#pragma unroll
            for (int h = 0; h < 2; h++) {
                const int row = m0 + wm * 64 + mi * 16 + g + h * 8;
                float x0 = acc[mi][ni][h * 2];
                float x1 = acc[mi][ni][h * 2 + 1];
                if (mode == 1) {
                    x0 = fmaxf(x0 + b1[col], 0.f);
                    x1 = fmaxf(x1 + b1[col + 1], 0.f);
                } else if (mode == 2) {
                    x0 += b1[col]; x1 += b1[col + 1];
                } else if (mode == 4) {
                    const float* ler = leb + (long)row * Cc;
                    x0 += lsr[col] + ler[col] + W2bg[col] + biasg[col];
                    x1 += lsr[col + 1] + ler[col + 1] + W2bg[col + 1] + biasg[col + 1];
                }
                if (mode == 0 || mode == 4) {
                    *(float2*)(Cf + (long)row * ldc + col) = make_float2(x0, x1);
                } else {
                    *(__half2*)(Ch + (long)row * ldc + col) = __floats2half2_rn(x0, x1);
                }
            }
        }
    }
}

// ---------------------------------------------------------------------------
// Round-14: fast W1 transpose. 128x128 tile per 256-thread block (16x fewer
// blocks than the 32x32 version), float4 loads, uint4 (8-half) stores,
// 66KB dynamic smem. W1th[c][e][d] = half(W1[c][d][e]).
// ---------------------------------------------------------------------------
#define TP_SMEM (128 * 129 * 4)   // 66048

__global__ void __launch_bounds__(256)
transpose_fast(const float* __restrict__ W1, __half* __restrict__ W1t)
{
    extern __shared__ float ts[];     // [128][129]
    const int c = blockIdx.z;
    const float* src = W1 + (size_t)c * HD;
    __half* dst = W1t + (size_t)c * HD;
    const int d0 = blockIdx.y * 128, e0 = blockIdx.x * 128;
    const int tid = threadIdx.x;

    // load 128 rows x 128 cols f32: each thread 16 float4
    {
        const int rg = tid >> 5;            // 0..7 -> 16 rows each
        const int cq = (tid & 31) * 4;      // col 0..124
#pragma unroll
        for (int i = 0; i < 16; i++) {
            const int r = rg * 16 + i;
            float4 v = *(const float4*)(src + (size_t)(d0 + r) * Dd + e0 + cq);
            float* t = ts + r * 129 + cq;
            t[0] = v.x; t[1] = v.y; t[2] = v.z; t[3] = v.w;
        }
    }
    __syncthreads();

    // store: out row = e (128 rows), cols = d in 8-half chunks (16 chunks/row)
    // 128*16 = 2048 tasks / 256 threads = 8 per thread
#pragma unroll
    for (int t = 0; t < 8; t++) {
        const int task = tid + t * 256;
        const int er = task >> 4;
        const int dc = (task & 15) * 8;
        uint32_t hp[4];
#pragma unroll
        for (int j = 0; j < 4; j++) {
            __half lo = __float2half_rn(ts[(dc + 2 * j) * 129 + er]);
            __half hi = __float2half_rn(ts[(dc + 2 * j + 1) * 129 + er]);
            hp[j] = (uint32_t)__half_as_ushort(lo) | ((uint32_t)__half_as_ushort(hi) << 16);
        }
        *(uint4*)(dst + (size_t)(e0 + er) * Dd + d0 + dc) =
            make_uint4(hp[0], hp[1], hp[2], hp[3]);
    }
}

// Fused f32->f16 conversion for all six tensors in ONE launch
__global__ void f2h_multi(const float* __restrict__ hidden,
                          const float* __restrict__ sw1, const float* __restrict__ ew1,
                          const float* __restrict__ sw2, const float* __restrict__ ew2,
                          const float* __restrict__ W2w,
                          __half* Xh, __half* w13, __half* w24, __half* W2h)
{
    const int total = BLD + 4 * HD + Cc * 2 * Dd;
    for (int i = blockIdx.x * blockDim.x + threadIdx.x; i < total;
         i += gridDim.x * blockDim.x) {
        int j = i;
        if (j < BLD) { Xh[j] = __float2half_rn(hidden[j]); continue; }
        j -= BLD;
        if (j < HD) { w13[j] = __float2half_rn(sw1[j]); continue; }
        j -= HD;
        if (j < HD) { w13[HD + j] = __float2half_rn(ew1[j]); continue; }
        j -= HD;
        if (j < HD) { w24[j] = __float2half_rn(sw2[j]); continue; }
        j -= HD;
        if (j < HD) { w24[HD + j] = __float2half_rn(ew2[j]); continue; }
        j -= HD;
        W2h[j] = __float2half_rn(W2w[j]);
    }
}

__global__ void biascpy(const float* a, const float* b, const float* c, const float* d,
                        float* b1x, float* b2x)
{
    int i = blockIdx.x * blockDim.x + threadIdx.x;
    if (i < Dd) {
        b1x[i] = a[i]; b1x[Dd + i] = b[i];
        b2x[i] = c[i]; b2x[Dd + i] = d[i];
    }
}

__global__ void fillh_k(__half* y, int n, unsigned seed)
{
    for (int i = blockIdx.x * blockDim.x + threadIdx.x; i < n; i += gridDim.x * blockDim.x) {
        unsigned v = (unsigned)i * 2654435761u + seed * 97u;
        y[i] = __float2half_rn((float)((v >> 16) & 1023) / 256.f - 2.f);
    }
}
__global__ void cmp_k(const float* a, const float* b, int n, int* bad)
{
    int i = blockIdx.x * blockDim.x + threadIdx.x;
    if (i < n) {
        float d = fabsf(a[i] - b[i]);
        if (!(d <= 0.25f + 0.01f * fabsf(a[i]))) atomicAdd(bad, 1);
    }
}

// ---------------------------------------------------------------------------
// tcgen05 kernel (NVRTC, sm_103a). Mainloop unchanged from round 13
// (TMA producers, 3-stage ring, M=256 dual-TMEM). Profile-validated.
// ---------------------------------------------------------------------------
static const char* TC_SRC = R"XX(
typedef unsigned int u32; typedef unsigned long long u64; typedef unsigned short u16;
#define MWAIT(a,p) do{ if(alive){ u32 ok=0; for(int t=0;t<4000&&!ok;t++){ \
  asm volatile("{\n\t.reg .pred P;\n\tmbarrier.try_wait.parity.acquire.cta.shared::cta.b64 P, [%1], %2, 0x989680;\n\tselp.b32 %0, 1, 0, P;\n\t}" \
    : "=r"(ok) : "r"(a), "r"(p) : "memory"); } alive = ok; } }while(0)
extern "C" __global__ void __launch_bounds__(288) gtc(
  const void* mA, const void* mB,
  void* Cv, long long scz, long long ldc,
  int mode, const float* b1, long long bstr,
  const float* Lsg, const float* Leg, const float* W2bg, const float* biasg)
{
  extern __shared__ char smem[];
  u32 raw; asm("{ .reg .u64 t; cvta.to.shared.u64 t, %1; cvt.u32.u64 %0, t; }":"=r"(raw):"l"(smem));
  const u32 data = (raw + 1023) & ~(u32)1023;
  const u32 ctrl = data + 196608;
  const u32 bfl[3] = {ctrl, ctrl + 8, ctrl + 16};
  const u32 bem[3] = {ctrl + 24, ctrl + 32, ctrl + 40};
  const u32 bdone = ctrl + 48, btm = ctrl + 56;
  const int tid = threadIdx.x, wid = tid >> 5;
  const int z = blockIdx.z;
  u32 alive = 1;
  float* Cf = (float*)Cv; u16* Ch = (u16*)Cv;
  if (mode == 4) Cf += (long long)z * (512*256);
  else { Cf += (long long)z * scz; Ch += (long long)z * scz; }
  const float* b1z = b1 + (long long)z * bstr;
  const int m0 = blockIdx.y * 256, n0 = blockIdx.x * 256;

  int ay = m0, az = 0, bx0 = 0, bz = 0;
  if (mode == 1)      { bz = z; }
  else if (mode == 2) { az = z; bz = z; }
  else if (mode == 5) { ay = m0 + z * 1024; bx0 = z * 768; }
  else if (mode == 3) { bz = z; }
  else if (mode == 4) { ay = 1024 + (z >> 9) * 512 + m0; bz = z; }

  if (tid == 0) {
    #pragma unroll
    for (int s = 0; s < 3; s++) {
      asm volatile("mbarrier.init.shared.b64 [%0], 1;"::"r"(bfl[s]):"memory");
      asm volatile("mbarrier.init.shared.b64 [%0], 1;"::"r"(bem[s]):"memory");
    }
    asm volatile("mbarrier.init.shared.b64 [%0], 1;"::"r"(bdone):"memory");
  }
  if (wid == 8) {
    asm volatile("tcgen05.alloc.cta_group::1.sync.aligned.shared::cta.b32 [%0], 512;"::"r"(btm):"memory");
    asm volatile("tcgen05.relinquish_alloc_permit.cta_group::1.sync.aligned;");
  }
  __syncthreads();
  u32 tmem; asm volatile("ld.shared.b32 %0, [%1];":"=r"(tmem):"r"(btm));

  if (tid == 0) {
    for (int k = 0; k < 12; k++) {
      const int s = k % 3;
      if (k >= 3) MWAIT(bem[s], ((k / 3) - 1) & 1);
      const u32 dstA = data + (u32)s * 65536;
      const u32 dstB = dstA + 32768;
      asm volatile("mbarrier.arrive.expect_tx.shared.b64 _, [%0], %1;"
                   :: "r"(bfl[s]), "r"(65536u) : "memory");
      asm volatile("cp.async.bulk.tensor.3d.shared::cta.global.tile.mbarrier::complete_tx::bytes "
                   "[%0], [%1, {%2, %3, %4}], [%5];"
                   :: "r"(dstA), "l"(mA), "r"(k * 64), "r"(ay), "r"(az), "r"(bfl[s]) : "memory");
      asm volatile("cp.async.bulk.tensor.3d.shared::cta.global.tile.mbarrier::complete_tx::bytes "
                   "[%0], [%1, {%2, %3, %4}], [%5];"
                   :: "r"(dstB), "l"(mB), "r"(bx0 + k * 64), "r"(n0), "r"(bz), "r"(bfl[s]) : "memory");
    }
  } else if (wid == 8 && (tid & 31) == 0) {
    const u64 base = (2ULL << 61) | (1ULL << 46) | (64ULL << 32) | (1ULL << 16);
    const u64 d0 = base | ((data >> 4) & 0x3FFF);
    const u32 idesc = (1u << 4) | (32u << 17) | (8u << 24);
    for (int k = 0; k < 12; k++) {
      const int s = k % 3;
      MWAIT(bfl[s], (k / 3) & 1);
      u64 dstage = d0 + (u64)s * 4096;
      u64 dA0 = dstage, dA1 = dstage + 1024, dB = dstage + 2048;
      #pragma unroll
      for (int i = 0; i < 4; i++) {
        u32 en = (u32)(k | i);
        asm volatile("{\n\t.reg .pred p;\n\tsetp.ne.u32 p, %4, 0;\n\t"
          "tcgen05.mma.cta_group::1.kind::f16 [%0], %1, %2, %3, {%5,%5,%5,%5}, p;\n\t}"
          ::"r"(tmem),"l"(dA0 + 2*i),"l"(dB + 2*i),"r"(idesc),"r"(en),"r"(0u):"memory");
      }
      #pragma unroll
      for (int i = 0; i < 4; i++) {
        u32 en = (u32)(k | i);
        asm volatile("{\n\t.reg .pred p;\n\tsetp.ne.u32 p, %4, 0;\n\t"
          "tcgen05.mma.cta_group::1.kind::f16 [%0], %1, %2, %3, {%5,%5,%5,%5}, p;\n\t}"
          ::"r"(tmem + 256),"l"(dA1 + 2*i),"l"(dB + 2*i),"r"(idesc),"r"(en),"r"(0u):"memory");
      }
      asm volatile("tcgen05.commit.cta_group::1.mbarrier::arrive::one.shared::cluster.b64 [%0];"::"r"(bem[s]):"memory");
    }
    asm volatile("tcgen05.commit.cta_group::1.mbarrier::arrive::one.shared::cluster.b64 [%0];"::"r"(bdone):"memory");
  }

  MWAIT(bdone, 0);
  asm volatile("tcgen05.fence::after_thread_sync;":::"memory");

  if (tid < 256) {
    const int grp = tid >> 7;
    const int lt = tid & 127;
    const long long row = m0 + grp * 128 + lt;
    const u32 tbase = tmem + (u32)grp * 256;
    const float* lsr = 0; const float* ler = 0;
    if (mode == 4) {
      lsr = Lsg + (long long)z * 256;
      ler = Leg + ((long long)(z >> 9) * 512 + row) * 256;
    }
    for (int nc = 0; nc < 8; nc++) {
      u32 r[32];
      asm volatile("tcgen05.ld.sync.aligned.32x32b.x32.b32 "
        "{%0,%1,%2,%3,%4,%5,%6,%7,%8,%9,%10,%11,%12,%13,%14,%15,"
        "%16,%17,%18,%19,%20,%21,%22,%23,%24,%25,%26,%27,%28,%29,%30,%31}, [%32];"
        : "=r"(r[0]),"=r"(r[1]),"=r"(r[2]),"=r"(r[3]),"=r"(r[4]),"=r"(r[5]),"=r"(r[6]),"=r"(r[7]),
          "=r"(r[8]),"=r"(r[9]),"=r"(r[10]),"=r"(r[11]),"=r"(r[12]),"=r"(r[13]),"=r"(r[14]),"=r"(r[15]),
          "=r"(r[16]),"=r"(r[17]),"=r"(r[18]),"=r"(r[19]),"=r"(r[20]),"=r"(r[21]),"=r"(r[22]),"=r"(r[23]),
          "=r"(r[24]),"=r"(r[25]),"=r"(r[26]),"=r"(r[27]),"=r"(r[28]),"=r"(r[29]),"=r"(r[30]),"=r"(r[31])
        : "r"(tbase + nc * 32));
      asm volatile("tcgen05.wait::ld.sync.aligned;":::"memory");
      const int nb = n0 + nc * 32;
      float v[32];
      #pragma unroll
      for (int c = 0; c < 32; c++) {
        float x; asm("mov.b32 %0, %1;" : "=f"(x) : "r"(r[c]));
        const int n = nb + c;
        if (mode == 1)      { x = x + b1z[n]; x = x > 0.f ? x : 0.f; }
        else if (mode == 2) x = x + b1z[n];
        else if (mode == 4) x += lsr[n] + ler[n] + W2bg[n] + biasg[n];
        v[c] = x;
      }
      if (mode == 0 || mode == 4 || mode == 5) {
        float* dst = Cf + row * ldc + nb;
        #pragma unroll
        for (int j = 0; j < 8; j++)
          asm volatile("st.global.v4.f32 [%0], {%1,%2,%3,%4};"
            ::"l"(dst + 4*j),"f"(v[4*j]),"f"(v[4*j+1]),"f"(v[4*j+2]),"f"(v[4*j+3]):"memory");
      } else {
        u16* dst = Ch + row * ldc + nb;
        u32 hp[16];
        #pragma unroll
        for (int j = 0; j < 16; j++) {
          asm("{\n\t.reg .b16 lo, hi;\n\tcvt.rn.f16.f32 lo, %1;\n\tcvt.rn.f16.f32 hi, %2;\n\t"
              "mov.b32 %0, {lo, hi};\n\t}" : "=r"(hp[j]) : "f"(v[2*j]), "f"(v[2*j+1]));
        }
        #pragma unroll
        for (int j = 0; j < 4; j++)
          asm volatile("st.global.v4.b32 [%0], {%1,%2,%3,%4};"
            ::"l"(dst + 8*j),"r"(hp[4*j]),"r"(hp[4*j+1]),"r"(hp[4*j+2]),"r"(hp[4*j+3]):"memory");
      }
    }
  }
  __syncthreads();
  if (wid == 8)
    asm volatile("tcgen05.dealloc.cta_group::1.sync.aligned.b32 %0, 512;"::"r"(tmem));
}
)XX";

// ---------------------------------------------------------------------------
// Runtime JIT plumbing
// ---------------------------------------------------------------------------
#define TC_SMEM 197760

#if defined(CUDA_API_PER_THREAD_DEFAULT_STREAM) || defined(__CUDA_API_PER_THREAD_DEFAULT_STREAM__)
#define HS ((void*)0x2)
#else
#define HS ((void*)0x1)
#endif

typedef int (*nvrtcCreate_t)(void**, const char*, const char*, int, const char* const*, const char* const*);
typedef int (*nvrtcCompile_t)(void*, int, const char* const*);
typedef int (*nvrtcGetSize_t)(void*, size_t*);
typedef int (*nvrtcGetData_t)(void*, char*);
typedef int (*cuModLoad_t)(void**, const void*);
typedef int (*cuModGetFn_t)(void**, void*, const char*);
typedef int (*cuFnSetAttr_t)(void*, int, int);
typedef int (*cuLaunch_t)(void*, unsigned, unsigned, unsigned, unsigned, unsigned, unsigned,
                          unsigned, void*, void**, void**);
typedef int (*cuTMEnc_t)(void*, int, unsigned, void*, const uint64_t*, const uint64_t*,
                         const uint32_t*, const uint32_t*, int, int, int, int);

static int g_init_done = 0;
static int g_use_tc = 0;
static void* g_fn = nullptr;
static cuLaunch_t p_launch = nullptr;

static int tc_gemm(int gx, int gy, int gz,
                   const void* mA, const void* mB,
                   void* C, long long scz, long long ldc, int mode,
                   const void* b1, long long bstr,
                   const void* Ls, const void* Le,
                   const void* W2b, const void* bias)
{
    void* args[12] = {(void*)&mA, (void*)&mB, (void*)&C, (void*)&scz, (void*)&ldc,
                      (void*)&mode, (void*)&b1, (void*)&bstr,
                      (void*)&Ls, (void*)&Le, (void*)&W2b, (void*)&bias};
    return p_launch(g_fn, gx, gy, gz, 288, 1, 1, TC_SMEM, HS, args, 0);
}

static void* try_dlopen(const char* const* names, int n) {
    for (int i = 0; i < n; i++) {
        void* h = dlopen(names[i], RTLD_NOW | RTLD_GLOBAL);
        if (h) return h;
    }
    return nullptr;
}

static int enc3(cuTMEnc_t f, void* map, void* addr,
                uint64_t d0, uint64_t d1, uint64_t d2,
                uint64_t s1b, uint64_t s2b)
{
    uint64_t dims[3] = {d0, d1, d2};
    uint64_t str[2] = {s1b, s2b};
    uint32_t box[3] = {64, 256, 1};
    uint32_t es[3] = {1, 1, 1};
    return f(map, 6, 3, addr, dims, str, box, es, 0, 3, 2, 0);
}

static void init_tc(__half* Xh, __half* w13h, __half* w24h, __half* W2h,
                    __half* W1th, __half* Htmp2, __half* HsHe, __half* Th,
                    float* LsLe, int* badp, unsigned char* dtm)
{
    const char* nvrtc_names[] = {"libnvrtc.so", "libnvrtc.so.13", "libnvrtc.so.12",
                                 "/usr/local/cuda/lib64/libnvrtc.so"};
    const char* cuda_names[] = {"libcuda.so.1", "libcuda.so"};
    void* hn = try_dlopen(nvrtc_names, 4);
    void* hc = try_dlopen(cuda_names, 2);
    if (!hn || !hc) { fprintf(stderr, "tcjit: dlopen failed\n"); return; }

    auto nCreate = (nvrtcCreate_t)dlsym(hn, "nvrtcCreateProgram");
    auto nCompile = (nvrtcCompile_t)dlsym(hn, "nvrtcCompileProgram");
    auto nCubSz = (nvrtcGetSize_t)dlsym(hn, "nvrtcGetCUBINSize");
    auto nCub = (nvrtcGetData_t)dlsym(hn, "nvrtcGetCUBIN");
    auto nLogSz = (nvrtcGetSize_t)dlsym(hn, "nvrtcGetProgramLogSize");
    auto nLog = (nvrtcGetData_t)dlsym(hn, "nvrtcGetProgramLog");
    auto mLoad = (cuModLoad_t)dlsym(hc, "cuModuleLoadData");
    auto mGetFn = (cuModGetFn_t)dlsym(hc, "cuModuleGetFunction");
    auto fAttr = (cuFnSetAttr_t)dlsym(hc, "cuFuncSetAttribute");
    auto tmEnc = (cuTMEnc_t)dlsym(hc, "cuTensorMapEncodeTiled");
    p_launch = (cuLaunch_t)dlsym(hc, "cuLaunchKernel");
    if (!nCreate || !nCompile || !nCubSz || !nCub || !mLoad || !mGetFn || !fAttr ||
        !p_launch || !tmEnc) {
        fprintf(stderr, "tcjit: dlsym failed\n"); return;
    }

    void* prog = nullptr;
    if (nCreate(&prog, TC_SRC, "tc.cu", 0, nullptr, nullptr)) {
        fprintf(stderr, "tcjit: create failed\n"); return;
    }
    const char* opts1[] = {"--gpu-architecture=sm_103a", "--std=c++14"};
    int cres = nCompile(prog, 2, opts1);
    if (cres) {
        if (nLogSz && nLog) {
            size_t ls = 0; nLogSz(prog, &ls);
            if (ls > 1) { char* lg = (char*)malloc(ls + 1); nLog(prog, lg); lg[ls] = 0;
                          fprintf(stderr, "tcjit: compile log:\n%s\n", lg); free(lg); }
        }
        fprintf(stderr, "tcjit: compile failed (%d)\n", cres);
        return;
    }
    size_t csz = 0;
    if (nCubSz(prog, &csz) || csz == 0) { fprintf(stderr, "tcjit: cubin size fail\n"); return; }
    char* cub = (char*)malloc(csz);
    nCub(prog, cub);
    void* mod = nullptr;
    int lr = mLoad(&mod, cub);
    free(cub);
    if (lr) { fprintf(stderr, "tcjit: module load failed %d\n", lr); return; }
    if (mGetFn(&g_fn, mod, "gtc")) { fprintf(stderr, "tcjit: getfn failed\n"); return; }
    fAttr(g_fn, 8, TC_SMEM);

    // ---- encode the 8 tensormaps ----
    static unsigned char hmaps[8 * 128] __attribute__((aligned(64)));
    memset(hmaps, 0, sizeof(hmaps));
    int e = 0;
    e |= enc3(tmEnc, hmaps + 0 * 128, Xh,    768, 1024, 1,    1536, (uint64_t)BLD * 2);
    e |= enc3(tmEnc, hmaps + 1 * 128, w13h,  768, 768,  2,    1536, (uint64_t)HD * 2);
    e |= enc3(tmEnc, hmaps + 2 * 128, Htmp2, 768, 1024, 2,    1536, (uint64_t)BLD * 2);
    e |= enc3(tmEnc, hmaps + 3 * 128, w24h,  768, 768,  2,    1536, (uint64_t)HD * 2);
    e |= enc3(tmEnc, hmaps + 4 * 128, HsHe,  768, 2048, 1,    1536, (uint64_t)2 * BLD * 2);
    e |= enc3(tmEnc, hmaps + 5 * 128, W2h,   1536, 256, 1,    3072, (uint64_t)Cc * 2 * Dd * 2);
    e |= enc3(tmEnc, hmaps + 6 * 128, W1th,  768, 768,  256,  1536, (uint64_t)HD * 2);
    e |= enc3(tmEnc, hmaps + 7 * 128, Th,    768, 256,  1024, 1536, (uint64_t)Cc * Dd * 2);
    if (e) { fprintf(stderr, "tcjit: tensormap encode failed %d\n", e); return; }
    cudaMemcpy(dtm, hmaps, sizeof(hmaps), cudaMemcpyHostToDevice);

    // ---- validation + diagnostic ----
    fillh_k<<<192, 256>>>(Xh, BLD, 1u);
    fillh_k<<<192, 256>>>(w13h, HD, 7u);
    gemm_h<<<dim3(2, 2, 1), 256, SMEM_BYTES>>>(Xh, 0, Dd, w13h, 0, Dd, (void*)LsLe, 0, Cc,
                                               0, nullptr, nullptr, nullptr, nullptr, nullptr);
    int dres = tc_gemm(3, 4, Cc, dtm + 4 * 128, dtm + 6 * 128,
                       Th, Dd, (long long)Cc * Dd, 3, 0, 0, 0, 0, 0, 0);
    if (dres) { fprintf(stderr, "tcjit: diag launch failed %d\n", dres); return; }
    int lres = tc_gemm(1, 1, 1, dtm + 0 * 128, dtm + 1 * 128,
                       LsLe + BLC, 0, Cc, 0, 0, 0, 0, 0, 0, 0);
    if (lres) { fprintf(stderr, "tcjit: launch failed %d\n", lres); return; }
    cudaMemset(badp, 0, sizeof(int));
    cmp_k<<<256, 256>>>(LsLe, LsLe + BLC, 256 * Cc, badp);
    cudaError_t serr = cudaDeviceSynchronize();
    if (serr != cudaSuccess) {
        fprintf(stderr, "tcjit: validation sync error: %s\n", cudaGetErrorString(serr));
        return;
    }
    int bad = 1 << 30;
    cudaMemcpy(&bad, badp, sizeof(int), cudaMemcpyDeviceToHost);
    fprintf(stderr, "tcjit: validation mismatches = %d / %d\n", bad, 256 * Cc);
    if (bad == 0) g_use_tc = 1;
}

extern "C" void kernel_launch(void* const* d_in, const int* in_sizes, int n_in,
                              void* d_out, int out_size)
{
    const float* hidden = (const float*)d_in[0];
    const float* sw1 = (const float*)d_in[1];
    const float* sb1 = (const float*)d_in[2];
    const float* sw2 = (const float*)d_in[3];
    const float* sb2 = (const float*)d_in[4];
    const float* ew1 = (const float*)d_in[5];
    const float* eb1 = (const float*)d_in[6];
    const float* ew2 = (const float*)d_in[7];
    const float* eb2 = (const float*)d_in[8];
    const float* W1  = (const float*)d_in[9];
    const float* W2w = (const float*)d_in[10];
    const float* W2b = (const float*)d_in[11];
    const float* bs  = (const float*)d_in[12];
    float* out = (float*)d_out;

    __half *Xh, *w13h, *w24h, *W2h, *W1th, *Htmp2, *HsHe, *Th;
    float *LsLe, *b1x, *b2x;
    int* badp;
    unsigned char* dtm;
    cudaGetSymbolAddress((void**)&Xh, g_Xh);
    cudaGetSymbolAddress((void**)&w13h, g_w13h);
    cudaGetSymbolAddress((void**)&w24h, g_w24h);
    cudaGetSymbolAddress((void**)&W2h, g_W2h);
    cudaGetSymbolAddress((void**)&W1th, g_W1th);
    cudaGetSymbolAddress((void**)&Htmp2, g_Htmp2);
    cudaGetSymbolAddress((void**)&HsHe, g_HsHe);
    cudaGetSymbolAddress((void**)&Th, g_Th);
    cudaGetSymbolAddress((void**)&LsLe, g_LsLe);
    cudaGetSymbolAddress((void**)&b1x, g_b1x);
    cudaGetSymbolAddress((void**)&b2x, g_b2x);
    cudaGetSymbolAddress((void**)&badp, g_bad);
    cudaGetSymbolAddress((void**)&dtm, g_tmaps);

    if (!g_init_done) {
        cudaFuncSetAttribute(gemm_h, cudaFuncAttributeMaxDynamicSharedMemorySize, SMEM_BYTES);
        cudaFuncSetAttribute(transpose_fast, cudaFuncAttributeMaxDynamicSharedMemorySize, TP_SMEM);
        init_tc(Xh, w13h, w24h, W2h, W1th, Htmp2, HsHe, Th, LsLe, badp, dtm);
        g_init_done = 1;
    }

    // fused prep
    f2h_multi<<<512, 256>>>(hidden, sw1, ew1, sw2, ew2, W2w, Xh, w13h, w24h, W2h);
    biascpy<<<3, 256>>>(sb1, eb1, sb2, eb2, b1x, b2x);
    transpose_fast<<<dim3(6, 6, Cc), 256, TP_SMEM>>>(W1, W1th);

    int tc_ok = 0;
    if (g_use_tc) {
        tc_ok = (tc_gemm(3, 4, 2, dtm + 0 * 128, dtm + 1 * 128,
                         Htmp2, BLD, Dd, 1, b1x, Dd, 0, 0, 0, 0) == 0);
        if (!tc_ok) g_use_tc = 0;
    }
    if (tc_ok) {
        tc_gemm(3, 4, 2, dtm + 2 * 128, dtm + 3 * 128,
                HsHe, BLD, Dd, 2, b2x, Dd, 0, 0, 0, 0);
        tc_gemm(1, 4, 2, dtm + 4 * 128, dtm + 5 * 128,
                LsLe, (long long)BLC, Cc, 5, 0, 0, 0, 0, 0, 0);
        tc_gemm(3, 4, Cc, dtm + 4 * 128, dtm + 6 * 128,
                Th, Dd, (long long)Cc * Dd, 3, 0, 0, 0, 0, 0, 0);
        tc_gemm(1, 2, BLn, dtm + 4 * 128, dtm + 7 * 128,
                out, 0, Cc, 4, 0, 0, LsLe, LsLe + BLC, W2b, bs);
    } else {
        const dim3 blk(256);
        gemm_h<<<dim3(6, 8, 1), blk, SMEM_BYTES>>>(Xh, 0, Dd, w13h, 0, Dd, Htmp2, 0, Dd,
                                                   1, sb1, nullptr, nullptr, nullptr, nullptr);
        gemm_h<<<dim3(6, 8, 1), blk, SMEM_BYTES>>>(Htmp2, 0, Dd, w24h, 0, Dd, HsHe, 0, Dd,
                                                   2, sb2, nullptr, nullptr, nullptr, nullptr);
        gemm_h<<<dim3(6, 8, 1), blk, SMEM_BYTES>>>(Xh, 0, Dd, w13h + HD, 0, Dd, Htmp2 + BLD, 0, Dd,
                                                   1, eb1, nullptr, nullptr, nullptr, nullptr);
        gemm_h<<<dim3(6, 8, 1), blk, SMEM_BYTES>>>(Htmp2 + BLD, 0, Dd, w24h + HD, 0, Dd, HsHe + BLD, 0, Dd,
                                                   2, eb2, nullptr, nullptr, nullptr, nullptr);
        gemm_h<<<dim3(2, 8, 1), blk, SMEM_BYTES>>>(HsHe, 0, Dd, W2h, 0, 2 * Dd, LsLe, 0, Cc,
                                                   0, nullptr, nullptr, nullptr, nullptr, nullptr);
        gemm_h<<<dim3(2, 8, 1), blk, SMEM_BYTES>>>(HsHe + BLD, 0, Dd, W2h + Dd, 0, 2 * Dd, LsLe + BLC, 0, Cc,
                                                   0, nullptr, nullptr, nullptr, nullptr, nullptr);
        gemm_h<<<dim3(6, 8, Cc), blk, SMEM_BYTES>>>(HsHe, 0, Dd,
                                                    W1th, (long)HD, Dd,
                                                    Th, (long)Dd, (long)Cc * Dd,
                                                    3, nullptr, nullptr, nullptr, nullptr, nullptr);
        gemm_h<<<dim3(2, 4, BLn), blk, SMEM_BYTES>>>(HsHe + BLD, 0, Dd, Th, 0, Dd, out, 0, Cc,
                                                     4, nullptr, LsLe, LsLe + BLC, W2b, bs);
    }
}

// round 15
// speedup vs baseline: 1.0181x; 1.0181x over previous
#include <cuda_runtime.h>
#include <cuda_fp16.h>
#include <cstdint>
#include <cstdio>
#include <cstdlib>
#include <cstring>
#include <dlfcn.h>

#define Dd 768
#define Cc 256
#define BLn 1024
#define HD (Dd * Dd)          // 589824
#define BLD (BLn * Dd)        // 786432
#define BLC (BLn * Cc)        // 262144

// Scratch (device globals: allocation-free rule; zero-initialized)
__device__ __half g_Xh[BLD];
__device__ __half g_w13h[2 * HD];                 // sw1 || ew1
__device__ __half g_w24h[2 * HD];                 // sw2 || ew2
__device__ __half g_W2h[Cc * 2 * Dd];
__device__ __half g_W1th[(size_t)Cc * Dd * Dd];   // now: NATIVE W1 in f16 [c][d][e]
__device__ __half g_Htmp2[2 * BLD];               // s-hidden || e-hidden
__device__ __half g_HsHe[2 * BLD];                // Hs || He  (2048 x 768)
__device__ __half g_Th[(size_t)BLn * Cc * Dd];    // U[j'][c][d] half
__device__ float  g_LsLe[2 * BLC];                // Ls || Le
__device__ float  g_b1x[2 * Dd];                  // sb1 || eb1
__device__ float  g_b2x[2 * Dd];                  // sb2 || eb2
__device__ int    g_bad;
__device__ __align__(128) unsigned char g_tmaps[8 * 128];   // CUtensorMaps

static __device__ __forceinline__ uint32_t smem_u32(const void* p) {
    uint32_t a;
    asm("{ .reg .u64 t; cvta.to.shared.u64 t, %1; cvt.u32.u64 %0, t; }" : "=r"(a) : "l"(p));
    return a;
}
static __device__ __forceinline__ void cp16(uint32_t dst, const void* src) {
    asm volatile("cp.async.cg.shared.global [%0], [%1], 16;" :: "r"(dst), "l"(src) : "memory");
}
static __device__ __forceinline__ void cp_commit() {
    asm volatile("cp.async.commit_group;" ::: "memory");
}
template <int N>
static __device__ __forceinline__ void cp_wait() {
    asm volatile("cp.async.wait_group %0;" :: "n"(N) : "memory");
}
static __device__ __forceinline__ void mma_f16(float& c0, float& c1, float& c2, float& c3,
                                               uint32_t a0, uint32_t a1, uint32_t a2, uint32_t a3,
                                               uint32_t b0, uint32_t b1) {
    asm volatile(
        "mma.sync.aligned.m16n8k16.row.col.f32.f16.f16.f32 "
        "{%0,%1,%2,%3}, {%4,%5,%6,%7}, {%8,%9}, {%0,%1,%2,%3};"
        : "+f"(c0), "+f"(c1), "+f"(c2), "+f"(c3)
        : "r"(a0), "r"(a1), "r"(a2), "r"(a3), "r"(b0), "r"(b1));
}

// ---------------------------------------------------------------------------
// Legacy fp16 mma.sync GEMM (fallback + validation reference; ~2022us path)
// NOTE: fallback now also uses the e-first contraction (native W1 f16),
// mode 4 adapted to z=(b,j), rows=i output addressing.
// ---------------------------------------------------------------------------
#define ROWH 72
#define ASTG (128 * ROWH)
#define SMEM_BYTES (4 * ASTG * 2 * 2 / 2)  // 73728

__global__ void __launch_bounds__(256, 2)
gemm_h(const __half* A, long saz, int lda,
       const __half* B, long sbz, int ldb,
       void* Cv, long scz, long ldc,
       int mode, const float* __restrict__ b1,
       const float* __restrict__ Lsg, const float* __restrict__ Leg,
       const float* __restrict__ W2bg, const float* __restrict__ biasg)
{
    extern __shared__ __half smh[];
    __half* As = smh;
    __half* Bs = smh + 2 * ASTG;
    const uint32_t sbase = smem_u32(smh);
    const uint32_t bbase = sbase + 2 * ASTG * 2;

    const int tid = threadIdx.x;
    const int z = blockIdx.z;
    float* Cf = (float*)Cv;
    __half* Ch = (__half*)Cv;
    long ldc_eff = ldc;
    if (mode == 4) {
        // z = (b, j): A = Hs rows b*512.., B = U[z], out rows = i (stride 512*256)
        A += (long)(z >> 9) * 512 * Dd;
        B += (long)z * Cc * Dd;
        Cf += ((long)(z >> 9) << 26) + (long)(z & 511) * Cc;
        ldc_eff = 512 * Cc;
    } else {
        A += z * saz; B += z * sbz;
        Cf += z * scz; Ch += z * scz;
    }
    const int m0 = blockIdx.y * 128, n0 = blockIdx.x * 128;

    const int pr = tid >> 3, pc = tid & 7;
    const __half* pa0 = A + (long)(m0 + pr) * lda + pc * 8;
    const __half* pb0 = B + (long)(n0 + pr) * ldb + pc * 8;
    const uint32_t qoff = (uint32_t)(pr * ROWH * 2 + pc * 16);
    const uint32_t qa0 = sbase + qoff;
    const uint32_t qb0 = bbase + qoff;
    const uint32_t stgb = ASTG * 2;

    float acc[4][4][4];
#pragma unroll
    for (int mi = 0; mi < 4; mi++)
#pragma unroll
        for (int ni = 0; ni < 4; ni++)
#pragma unroll
            for (int r = 0; r < 4; r++) acc[mi][ni][r] = 0.f;

    const int lane = tid & 31, w = tid >> 5;
    const int g = lane >> 2, tig = lane & 3;
    const int wm = w & 1, wn = w >> 1;

#pragma unroll
    for (int i = 0; i < 4; i++) {
        cp16(qa0 + i * (32 * ROWH * 2), pa0 + (long)(32 * i) * lda);
        cp16(qb0 + i * (32 * ROWH * 2), pb0 + (long)(32 * i) * ldb);
    }
    cp_commit();

    for (int k0 = 0; k0 < 12; k0++) {
        cp_wait<0>();
        __syncthreads();
        if (k0 + 1 < 12) {
            const uint32_t so = ((k0 + 1) & 1) * stgb;
            const long go = (long)(k0 + 1) * 64;
#pragma unroll
            for (int i = 0; i < 4; i++) {
                cp16(qa0 + so + i * (32 * ROWH * 2), pa0 + (long)(32 * i) * lda + go);
                cp16(qb0 + so + i * (32 * ROWH * 2), pb0 + (long)(32 * i) * ldb + go);
            }
            cp_commit();
        }

        const __half* aw = As + (k0 & 1) * ASTG + (wm * 64) * ROWH;
        const __half* bw = Bs + (k0 & 1) * ASTG + (wn * 32) * ROWH;

#pragma unroll
        for (int ks = 0; ks < 4; ks++) {
            const int kh = ks * 16 + 2 * tig;
            uint32_t af[4][4], bf[4][2];
#pragma unroll
            for (int mi = 0; mi < 4; mi++) {
                const __half* p = aw + (mi * 16 + g) * ROWH + kh;
                af[mi][0] = *(const uint32_t*)(p);
                af[mi][1] = *(const uint32_t*)(p + 8 * ROWH);
                af[mi][2] = *(const uint32_t*)(p + 8);
                af[mi][3] = *(const uint32_t*)(p + 8 * ROWH + 8);
            }
#pragma unroll
            for (int ni = 0; ni < 4; ni++) {
                const __half* p = bw + (ni * 8 + g) * ROWH + kh;
                bf[ni][0] = *(const uint32_t*)(p);
                bf[ni][1] = *(const uint32_t*)(p + 8);
            }
#pragma unroll
            for (int mi = 0; mi < 4; mi++)
#pragma unroll
                for (int ni = 0; ni < 4; ni++)
                    mma_f16(acc[mi][ni][0], acc[mi][ni][1], acc[mi][ni][2], acc[mi][ni][3],
                            af[mi][0], af[mi][1], af[mi][2], af[mi][3],
                            bf[ni][0], bf[ni][1]);
        }
    }

    const float* lsr = nullptr; const float* leb = nullptr;
    if (mode == 4) {
        lsr = Lsg + (long)z * Cc;                       // per-z (Le passed here)
        leb = Leg + (long)(z >> 9) * 512 * Cc;          // per-row (Ls passed here)
    }
#pragma unroll
    for (int mi = 0; mi < 4; mi++) {
#pragma unroll
        for (int ni = 0; ni < 4; ni++) {
            const int col = n0 + wn * 32 + ni * 8 + tig * 2;
#pragma unroll
            for (int h = 0; h < 2; h++) {
                const int row = m0 + wm * 64 + mi * 16 + g + h * 8;
                float x0 = acc[mi][ni][h * 2];
                float x1 = acc[mi][ni][h * 2 + 1];
                if (mode == 1) {
                    x0 = fmaxf(x0 + b1[col], 0.f);
                    x1 = fmaxf(x1 + b1[col + 1], 0.f);
                } else if (mode == 2) {
                    x0 += b1[col]; x1 += b1[col + 1];
                } else if (mode == 4) {
                    const float* ler = leb + (long)row * Cc;
                    x0 += lsr[col] + ler[col] + W2bg[col] + biasg[col];
                    x1 += lsr[col + 1] + ler[col + 1] + W2bg[col + 1] + biasg[col + 1];
                }
                if (mode == 0 || mode == 4) {
                    *(float2*)(Cf + (long)row * ldc_eff + col) = make_float2(x0, x1);
                } else {
                    *(__half2*)(Ch + (long)row * ldc_eff + col) = __floats2half2_rn(x0, x1);
                }
            }
        }
    }
}

// ---------------------------------------------------------------------------
// Round-15: W1 f32 -> f16 NATIVE copy (replaces the transpose entirely).
// Pure streaming: float4 x2 reads -> uint4 packed-half write, grid-stride.
// ---------------------------------------------------------------------------
__global__ void __launch_bounds__(256)
f2h_w1(const float* __restrict__ W1, __half* __restrict__ W1h)
{
    const long long n8 = (long long)Cc * HD / 8;   // 18,874,368
    for (long long i = blockIdx.x * (long long)blockDim.x + threadIdx.x; i < n8;
         i += (long long)gridDim.x * blockDim.x) {
        const float4 a = *(const float4*)(W1 + i * 8);
        const float4 b = *(const float4*)(W1 + i * 8 + 4);
        uint32_t h0, h1, h2, h3;
        asm("{.reg .b16 l,h; cvt.rn.f16.f32 l,%1; cvt.rn.f16.f32 h,%2; mov.b32 %0,{l,h};}"
            : "=r"(h0) : "f"(a.x), "f"(a.y));
        asm("{.reg .b16 l,h; cvt.rn.f16.f32 l,%1; cvt.rn.f16.f32 h,%2; mov.b32 %0,{l,h};}"
            : "=r"(h1) : "f"(a.z), "f"(a.w));
        asm("{.reg .b16 l,h; cvt.rn.f16.f32 l,%1; cvt.rn.f16.f32 h,%2; mov.b32 %0,{l,h};}"
            : "=r"(h2) : "f"(b.x), "f"(b.y));
        asm("{.reg .b16 l,h; cvt.rn.f16.f32 l,%1; cvt.rn.f16.f32 h,%2; mov.b32 %0,{l,h};}"
            : "=r"(h3) : "f"(b.z), "f"(b.w));
        *(uint4*)(W1h + i * 8) = make_uint4(h0, h1, h2, h3);
    }
}

// Fused f32->f16 conversion for the six small tensors in ONE launch
__global__ void f2h_multi(const float* __restrict__ hidden,
                          const float* __restrict__ sw1, const float* __restrict__ ew1,
                          const float* __restrict__ sw2, const float* __restrict__ ew2,
                          const float* __restrict__ W2w,
                          __half* Xh, __half* w13, __half* w24, __half* W2h)
{
    const int total = BLD + 4 * HD + Cc * 2 * Dd;
    for (int i = blockIdx.x * blockDim.x + threadIdx.x; i < total;
         i += gridDim.x * blockDim.x) {
        int j = i;
        if (j < BLD) { Xh[j] = __float2half_rn(hidden[j]); continue; }
        j -= BLD;
        if (j < HD) { w13[j] = __float2half_rn(sw1[j]); continue; }
        j -= HD;
        if (j < HD) { w13[HD + j] = __float2half_rn(ew1[j]); continue; }
        j -= HD;
        if (j < HD) { w24[j] = __float2half_rn(sw2[j]); continue; }
        j -= HD;
        if (j < HD) { w24[HD + j] = __float2half_rn(ew2[j]); continue; }
        j -= HD;
        W2h[j] = __float2half_rn(W2w[j]);
    }
}

__global__ void biascpy(const float* a, const float* b, const float* c, const float* d,
                        float* b1x, float* b2x)
{
    int i = blockIdx.x * blockDim.x + threadIdx.x;
    if (i < Dd) {
        b1x[i] = a[i]; b1x[Dd + i] = b[i];
        b2x[i] = c[i]; b2x[Dd + i] = d[i];
    }
}

__global__ void fillh_k(__half* y, int n, unsigned seed)
{
    for (int i = blockIdx.x * blockDim.x + threadIdx.x; i < n; i += gridDim.x * blockDim.x) {
        unsigned v = (unsigned)i * 2654435761u + seed * 97u;
        y[i] = __float2half_rn((float)((v >> 16) & 1023) / 256.f - 2.f);
    }
}
__global__ void cmp_k(const float* a, const float* b, int n, int* bad)
{
    int i = blockIdx.x * blockDim.x + threadIdx.x;
    if (i < n) {
        float d = fabsf(a[i] - b[i]);
        if (!(d <= 0.25f + 0.01f * fabsf(a[i]))) atomicAdd(bad, 1);
    }
}

// ---------------------------------------------------------------------------
// tcgen05 kernel (NVRTC, sm_103a). Mainloop identical to rounds 13/14.
// Round-15 changes are COORDINATE-ONLY (e-first contraction):
//  mode 3 (phase A'): A = He rows (1024+m0) of HsHe, B = native W1h slice z=c,
//                     out U[j'][c][d] (same store pattern as before).
//  mode 4 (phase B'): z=(b,j), A = Hs rows ((z>>9)*512+m0), B = U slice z,
//                     out rows = i with row stride 512*256, base z-dependent;
//                     per-z linear vec = Le, per-row vec = Ls (swapped args).
// ---------------------------------------------------------------------------
static const char* TC_SRC = R"XX(
typedef unsigned int u32; typedef unsigned long long u64; typedef unsigned short u16;
#define MWAIT(a,p) do{ if(alive){ u32 ok=0; for(int t=0;t<4000&&!ok;t++){ \
  asm volatile("{\n\t.reg .pred P;\n\tmbarrier.try_wait.parity.acquire.cta.shared::cta.b64 P, [%1], %2, 0x989680;\n\tselp.b32 %0, 1, 0, P;\n\t}" \
    : "=r"(ok) : "r"(a), "r"(p) : "memory"); } alive = ok; } }while(0)
extern "C" __global__ void __launch_bounds__(288) gtc(
  const void* mA, const void* mB,
  void* Cv, long long scz, long long ldc,
  int mode, const float* b1, long long bstr,
  const float* Lsg, const float* Leg, const float* W2bg, const float* biasg)
{
  extern __shared__ char smem[];
  u32 raw; asm("{ .reg .u64 t; cvta.to.shared.u64 t, %1; cvt.u32.u64 %0, t; }":"=r"(raw):"l"(smem));
  const u32 data = (raw + 1023) & ~(u32)1023;
  const u32 ctrl = data + 196608;
  const u32 bfl[3] = {ctrl, ctrl + 8, ctrl + 16};
  const u32 bem[3] = {ctrl + 24, ctrl + 32, ctrl + 40};
  const u32 bdone = ctrl + 48, btm = ctrl + 56;
  const int tid = threadIdx.x, wid = tid >> 5;
  const int z = blockIdx.z;
  u32 alive = 1;
  float* Cf = (float*)Cv; u16* Ch = (u16*)Cv;
  if (mode == 4) Cf += (((long long)(z >> 9)) << 26) + (long long)(z & 511) * 256;
  else { Cf += (long long)z * scz; Ch += (long long)z * scz; }
  const float* b1z = b1 + (long long)z * bstr;
  const int m0 = blockIdx.y * 256, n0 = blockIdx.x * 256;

  int ay = m0, az = 0, bx0 = 0, bz = 0;
  if (mode == 1)      { bz = z; }
  else if (mode == 2) { az = z; bz = z; }
  else if (mode == 5) { ay = m0 + z * 1024; bx0 = z * 768; }
  else if (mode == 3) { ay = 1024 + m0; bz = z; }
  else if (mode == 4) { ay = (z >> 9) * 512 + m0; bz = z; }

  if (tid == 0) {
    #pragma unroll
    for (int s = 0; s < 3; s++) {
      asm volatile("mbarrier.init.shared.b64 [%0], 1;"::"r"(bfl[s]):"memory");
      asm volatile("mbarrier.init.shared.b64 [%0], 1;"::"r"(bem[s]):"memory");
    }
    asm volatile("mbarrier.init.shared.b64 [%0], 1;"::"r"(bdone):"memory");
  }
  if (wid == 8) {
    asm volatile("tcgen05.alloc.cta_group::1.sync.aligned.shared::cta.b32 [%0], 512;"::"r"(btm):"memory");
    asm volatile("tcgen05.relinquish_alloc_permit.cta_group::1.sync.aligned;");
  }
  __syncthreads();
  u32 tmem; asm volatile("ld.shared.b32 %0, [%1];":"=r"(tmem):"r"(btm));

  if (tid == 0) {
    for (int k = 0; k < 12; k++) {
      const int s = k % 3;
      if (k >= 3) MWAIT(bem[s], ((k / 3) - 1) & 1);
      const u32 dstA = data + (u32)s * 65536;
      const u32 dstB = dstA + 32768;
      asm volatile("mbarrier.arrive.expect_tx.shared.b64 _, [%0], %1;"
                   :: "r"(bfl[s]), "r"(65536u) : "memory");
      asm volatile("cp.async.bulk.tensor.3d.shared::cta.global.tile.mbarrier::complete_tx::bytes "
                   "[%0], [%1, {%2, %3, %4}], [%5];"
                   :: "r"(dstA), "l"(mA), "r"(k * 64), "r"(ay), "r"(az), "r"(bfl[s]) : "memory");
      asm volatile("cp.async.bulk.tensor.3d.shared::cta.global.tile.mbarrier::complete_tx::bytes "
                   "[%0], [%1, {%2, %3, %4}], [%5];"
                   :: "r"(dstB), "l"(mB), "r"(bx0 + k * 64), "r"(n0), "r"(bz), "r"(bfl[s]) : "memory");
    }
  } else if (wid == 8 && (tid & 31) == 0) {
    const u64 base = (2ULL << 61) | (1ULL << 46) | (64ULL << 32) | (1ULL << 16);
    const u64 d0 = base | ((data >> 4) & 0x3FFF);
    const u32 idesc = (1u << 4) | (32u << 17) | (8u << 24);
    for (int k = 0; k < 12; k++) {
      const int s = k % 3;
      MWAIT(bfl[s], (k / 3) & 1);
      u64 dstage = d0 + (u64)s * 4096;
      u64 dA0 = dstage, dA1 = dstage + 1024, dB = dstage + 2048;
      #pragma unroll
      for (int i = 0; i < 4; i++) {
        u32 en = (u32)(k | i);
        asm volatile("{\n\t.reg .pred p;\n\tsetp.ne.u32 p, %4, 0;\n\t"
          "tcgen05.mma.cta_group::1.kind::f16 [%0], %1, %2, %3, {%5,%5,%5,%5}, p;\n\t}"
          ::"r"(tmem),"l"(dA0 + 2*i),"l"(dB + 2*i),"r"(idesc),"r"(en),"r"(0u):"memory");
      }
      #pragma unroll
      for (int i = 0; i < 4; i++) {
        u32 en = (u32)(k | i);
        asm volatile("{\n\t.reg .pred p;\n\tsetp.ne.u32 p, %4, 0;\n\t"
          "tcgen05.mma.cta_group::1.kind::f16 [%0], %1, %2, %3, {%5,%5,%5,%5}, p;\n\t}"
          ::"r"(tmem + 256),"l"(dA1 + 2*i),"l"(dB + 2*i),"r"(idesc),"r"(en),"r"(0u):"memory");
      }
      asm volatile("tcgen05.commit.cta_group::1.mbarrier::arrive::one.shared::cluster.b64 [%0];"::"r"(bem[s]):"memory");
    }
    asm volatile("tcgen05.commit.cta_group::1.mbarrier::arrive::one.shared::cluster.b64 [%0];"::"r"(bdone):"memory");
  }

  MWAIT(bdone, 0);
  asm volatile("tcgen05.fence::after_thread_sync;":::"memory");

  if (tid < 256) {
    const int grp = tid >> 7;
    const int lt = tid & 127;
    const long long row = m0 + grp * 128 + lt;
    const u32 tbase = tmem + (u32)grp * 256;
    const float* lsr = 0; const float* ler = 0;
    if (mode == 4) {
      lsr = Lsg + (long long)z * 256;                       // per-z (Le)
      ler = Leg + ((long long)(z >> 9) * 512 + row) * 256;  // per-row (Ls)
    }
    for (int nc = 0; nc < 8; nc++) {
      u32 r[32];
      asm volatile("tcgen05.ld.sync.aligned.32x32b.x32.b32 "
        "{%0,%1,%2,%3,%4,%5,%6,%7,%8,%9,%10,%11,%12,%13,%14,%15,"
        "%16,%17,%18,%19,%20,%21,%22,%23,%24,%25,%26,%27,%28,%29,%30,%31}, [%32];"
        : "=r"(r[0]),"=r"(r[1]),"=r"(r[2]),"=r"(r[3]),"=r"(r[4]),"=r"(r[5]),"=r"(r[6]),"=r"(r[7]),
          "=r"(r[8]),"=r"(r[9]),"=r"(r[10]),"=r"(r[11]),"=r"(r[12]),"=r"(r[13]),"=r"(r[14]),"=r"(r[15]),
          "=r"(r[16]),"=r"(r[17]),"=r"(r[18]),"=r"(r[19]),"=r"(r[20]),"=r"(r[21]),"=r"(r[22]),"=r"(r[23]),
          "=r"(r[24]),"=r"(r[25]),"=r"(r[26]),"=r"(r[27]),"=r"(r[28]),"=r"(r[29]),"=r"(r[30]),"=r"(r[31])
        : "r"(tbase + nc * 32));
      asm volatile("tcgen05.wait::ld.sync.aligned;":::"memory");
      const int nb = n0 + nc * 32;
      float v[32];
      #pragma unroll
      for (int c = 0; c < 32; c++) {
        float x; asm("mov.b32 %0, %1;" : "=f"(x) : "r"(r[c]));
        const int n = nb + c;
        if (mode == 1)      { x = x + b1z[n]; x = x > 0.f ? x : 0.f; }
        else if (mode == 2) x = x + b1z[n];
        else if (mode == 4) x += lsr[n] + ler[n] + W2bg[n] + biasg[n];
        v[c] = x;
      }
      if (mode == 0 || mode == 4 || mode == 5) {
        float* dst = Cf + row * ldc + nb;
        #pragma unroll
        for (int j = 0; j < 8; j++)
          asm volatile("st.global.v4.f32 [%0], {%1,%2,%3,%4};"
            ::"l"(dst + 4*j),"f"(v[4*j]),"f"(v[4*j+1]),"f"(v[4*j+2]),"f"(v[4*j+3]):"memory");
      } else {
        u16* dst = Ch + row * ldc + nb;
        u32 hp[16];
        #pragma unroll
        for (int j = 0; j < 16; j++) {
          asm("{\n\t.reg .b16 lo, hi;\n\tcvt.rn.f16.f32 lo, %1;\n\tcvt.rn.f16.f32 hi, %2;\n\t"
              "mov.b32 %0, {lo, hi};\n\t}" : "=r"(hp[j]) : "f"(v[2*j]), "f"(v[2*j+1]));
        }
        #pragma unroll
        for (int j = 0; j < 4; j++)
          asm volatile("st.global.v4.b32 [%0], {%1,%2,%3,%4};"
            ::"l"(dst + 8*j),"r"(hp[4*j]),"r"(hp[4*j+1]),"r"(hp[4*j+2]),"r"(hp[4*j+3]):"memory");
      }
    }
  }
  __syncthreads();
  if (wid == 8)
    asm volatile("tcgen05.dealloc.cta_group::1.sync.aligned.b32 %0, 512;"::"r"(tmem));
}
)XX";

// ---------------------------------------------------------------------------
// Runtime JIT plumbing
// ---------------------------------------------------------------------------
#define TC_SMEM 197760

#if defined(CUDA_API_PER_THREAD_DEFAULT_STREAM) || defined(__CUDA_API_PER_THREAD_DEFAULT_STREAM__)
#define HS ((void*)0x2)
#else
#define HS ((void*)0x1)
#endif

typedef int (*nvrtcCreate_t)(void**, const char*, const char*, int, const char* const*, const char* const*);
typedef int (*nvrtcCompile_t)(void*, int, const char* const*);
typedef int (*nvrtcGetSize_t)(void*, size_t*);
typedef int (*nvrtcGetData_t)(void*, char*);
typedef int (*cuModLoad_t)(void**, const void*);
typedef int (*cuModGetFn_t)(void**, void*, const char*);
typedef int (*cuFnSetAttr_t)(void*, int, int);
typedef int (*cuLaunch_t)(void*, unsigned, unsigned, unsigned, unsigned, unsigned, unsigned,
                          unsigned, void*, void**, void**);
typedef int (*cuTMEnc_t)(void*, int, unsigned, void*, const uint64_t*, const uint64_t*,
                         const uint32_t*, const uint32_t*, int, int, int, int);

static int g_init_done = 0;
static int g_use_tc = 0;
static void* g_fn = nullptr;
static cuLaunch_t p_launch = nullptr;

static int tc_gemm(int gx, int gy, int gz,
                   const void* mA, const void* mB,
                   void* C, long long scz, long long ldc, int mode,
                   const void* b1, long long bstr,
                   const void* Ls, const void* Le,
                   const void* W2b, const void* bias)
{
    void* args[12] = {(void*)&mA, (void*)&mB, (void*)&C, (void*)&scz, (void*)&ldc,
                      (void*)&mode, (void*)&b1, (void*)&bstr,
                      (void*)&Ls, (void*)&Le, (void*)&W2b, (void*)&bias};
    return p_launch(g_fn, gx, gy, gz, 288, 1, 1, TC_SMEM, HS, args, 0);
}

static void* try_dlopen(const char* const* names, int n) {
    for (int i = 0; i < n; i++) {
        void* h = dlopen(names[i], RTLD_NOW | RTLD_GLOBAL);
        if (h) return h;
    }
    return nullptr;
}

static int enc3(cuTMEnc_t f, void* map, void* addr,
                uint64_t d0, uint64_t d1, uint64_t d2,
                uint64_t s1b, uint64_t s2b)
{
    uint64_t dims[3] = {d0, d1, d2};
    uint64_t str[2] = {s1b, s2b};
    uint32_t box[3] = {64, 256, 1};
    uint32_t es[3] = {1, 1, 1};
    return f(map, 6, 3, addr, dims, str, box, es, 0, 3, 2, 0);
}

static void init_tc(__half* Xh, __half* w13h, __half* w24h, __half* W2h,
                    __half* W1h, __half* Htmp2, __half* HsHe, __half* Th,
                    float* LsLe, int* badp, unsigned char* dtm)
{
    const char* nvrtc_names[] = {"libnvrtc.so", "libnvrtc.so.13", "libnvrtc.so.12",
                                 "/usr/local/cuda/lib64/libnvrtc.so"};
    const char* cuda_names[] = {"libcuda.so.1", "libcuda.so"};
    void* hn = try_dlopen(nvrtc_names, 4);
    void* hc = try_dlopen(cuda_names, 2);
    if (!hn || !hc) { fprintf(stderr, "tcjit: dlopen failed\n"); return; }

    auto nCreate = (nvrtcCreate_t)dlsym(hn, "nvrtcCreateProgram");
    auto nCompile = (nvrtcCompile_t)dlsym(hn, "nvrtcCompileProgram");
    auto nCubSz = (nvrtcGetSize_t)dlsym(hn, "nvrtcGetCUBINSize");
    auto nCub = (nvrtcGetData_t)dlsym(hn, "nvrtcGetCUBIN");
    auto nLogSz = (nvrtcGetSize_t)dlsym(hn, "nvrtcGetProgramLogSize");
    auto nLog = (nvrtcGetData_t)dlsym(hn, "nvrtcGetProgramLog");
    auto mLoad = (cuModLoad_t)dlsym(hc, "cuModuleLoadData");
    auto mGetFn = (cuModGetFn_t)dlsym(hc, "cuModuleGetFunction");
    auto fAttr = (cuFnSetAttr_t)dlsym(hc, "cuFuncSetAttribute");
    auto tmEnc = (cuTMEnc_t)dlsym(hc, "cuTensorMapEncodeTiled");
    p_launch = (cuLaunch_t)dlsym(hc, "cuLaunchKernel");
    if (!nCreate || !nCompile || !nCubSz || !nCub || !mLoad || !mGetFn || !fAttr ||
        !p_launch || !tmEnc) {
        fprintf(stderr, "tcjit: dlsym failed\n"); return;
    }

    void* prog = nullptr;
    if (nCreate(&prog, TC_SRC, "tc.cu", 0, nullptr, nullptr)) {
        fprintf(stderr, "tcjit: create failed\n"); return;
    }
    const char* opts1[] = {"--gpu-architecture=sm_103a", "--std=c++14"};
    int cres = nCompile(prog, 2, opts1);
    if (cres) {
        if (nLogSz && nLog) {
            size_t ls = 0; nLogSz(prog, &ls);
            if (ls > 1) { char* lg = (char*)malloc(ls + 1); nLog(prog, lg); lg[ls] = 0;
                          fprintf(stderr, "tcjit: compile log:\n%s\n", lg); free(lg); }
        }
        fprintf(stderr, "tcjit: compile failed (%d)\n", cres);
        return;
    }
    size_t csz = 0;
    if (nCubSz(prog, &csz) || csz == 0) { fprintf(stderr, "tcjit: cubin size fail\n"); return; }
    char* cub = (char*)malloc(csz);
    nCub(prog, cub);
    void* mod = nullptr;
    int lr = mLoad(&mod, cub);
    free(cub);
    if (lr) { fprintf(stderr, "tcjit: module load failed %d\n", lr); return; }
    if (mGetFn(&g_fn, mod, "gtc")) { fprintf(stderr, "tcjit: getfn failed\n"); return; }
    fAttr(g_fn, 8, TC_SMEM);

    // ---- encode the 8 tensormaps ----
    static unsigned char hmaps[8 * 128] __attribute__((aligned(64)));
    memset(hmaps, 0, sizeof(hmaps));
    int e = 0;
    e |= enc3(tmEnc, hmaps + 0 * 128, Xh,    768, 1024, 1,    1536, (uint64_t)BLD * 2);
    e |= enc3(tmEnc, hmaps + 1 * 128, w13h,  768, 768,  2,    1536, (uint64_t)HD * 2);
    e |= enc3(tmEnc, hmaps + 2 * 128, Htmp2, 768, 1024, 2,    1536, (uint64_t)BLD * 2);
    e |= enc3(tmEnc, hmaps + 3 * 128, w24h,  768, 768,  2,    1536, (uint64_t)HD * 2);
    e |= enc3(tmEnc, hmaps + 4 * 128, HsHe,  768, 2048, 1,    1536, (uint64_t)2 * BLD * 2);
    e |= enc3(tmEnc, hmaps + 5 * 128, W2h,   1536, 256, 1,    3072, (uint64_t)Cc * 2 * Dd * 2);
    e |= enc3(tmEnc, hmaps + 6 * 128, W1h,   768, 768,  256,  1536, (uint64_t)HD * 2);
    e |= enc3(tmEnc, hmaps + 7 * 128, Th,    768, 256,  1024, 1536, (uint64_t)Cc * Dd * 2);
    if (e) { fprintf(stderr, "tcjit: tensormap encode failed %d\n", e); return; }
    cudaMemcpy(dtm, hmaps, sizeof(hmaps), cudaMemcpyHostToDevice);

    // ---- validation + diagnostic ----
    fillh_k<<<192, 256>>>(Xh, BLD, 1u);
    fillh_k<<<192, 256>>>(w13h, HD, 7u);
    gemm_h<<<dim3(2, 2, 1), 256, SMEM_BYTES>>>(Xh, 0, Dd, w13h, 0, Dd, (void*)LsLe, 0, Cc,
                                               0, nullptr, nullptr, nullptr, nullptr, nullptr);
    int dres = tc_gemm(3, 4, Cc, dtm + 4 * 128, dtm + 6 * 128,
                       Th, Dd, (long long)Cc * Dd, 3, 0, 0, 0, 0, 0, 0);
    if (dres) { fprintf(stderr, "tcjit: diag launch failed %d\n", dres); return; }
    int lres = tc_gemm(1, 1, 1, dtm + 0 * 128, dtm + 1 * 128,
                       LsLe + BLC, 0, Cc, 0, 0, 0, 0, 0, 0, 0);
    if (lres) { fprintf(stderr, "tcjit: launch failed %d\n", lres); return; }
    cudaMemset(badp, 0, sizeof(int));
    cmp_k<<<256, 256>>>(LsLe, LsLe + BLC, 256 * Cc, badp);
    cudaError_t serr = cudaDeviceSynchronize();
    if (serr != cudaSuccess) {
        fprintf(stderr, "tcjit: validation sync error: %s\n", cudaGetErrorString(serr));
        return;
    }
    int bad = 1 << 30;
    cudaMemcpy(&bad, badp, sizeof(int), cudaMemcpyDeviceToHost);
    fprintf(stderr, "tcjit: validation mismatches = %d / %d\n", bad, 256 * Cc);
    if (bad == 0) g_use_tc = 1;
}

extern "C" void kernel_launch(void* const* d_in, const int* in_sizes, int n_in,
                              void* d_out, int out_size)
{
    const float* hidden = (const float*)d_in[0];
    const float* sw1 = (const float*)d_in[1];
    const float* sb1 = (const float*)d_in[2];
    const float* sw2 = (const float*)d_in[3];
    const float* sb2 = (const float*)d_in[4];
    const float* ew1 = (const float*)d_in[5];
    const float* eb1 = (const float*)d_in[6];
    const float* ew2 = (const float*)d_in[7];
    const float* eb2 = (const float*)d_in[8];
    const float* W1  = (const float*)d_in[9];
    const float* W2w = (const float*)d_in[10];
    const float* W2b = (const float*)d_in[11];
    const float* bs  = (const float*)d_in[12];
    float* out = (float*)d_out;

    __half *Xh, *w13h, *w24h, *W2h, *W1h, *Htmp2, *HsHe, *Th;
    float *LsLe, *b1x, *b2x;
    int* badp;
    unsigned char* dtm;
    cudaGetSymbolAddress((void**)&Xh, g_Xh);
    cudaGetSymbolAddress((void**)&w13h, g_w13h);
    cudaGetSymbolAddress((void**)&w24h, g_w24h);
    cudaGetSymbolAddress((void**)&W2h, g_W2h);
    cudaGetSymbolAddress((void**)&W1h, g_W1th);
    cudaGetSymbolAddress((void**)&Htmp2, g_Htmp2);
    cudaGetSymbolAddress((void**)&HsHe, g_HsHe);
    cudaGetSymbolAddress((void**)&Th, g_Th);
    cudaGetSymbolAddress((void**)&LsLe, g_LsLe);
    cudaGetSymbolAddress((void**)&b1x, g_b1x);
    cudaGetSymbolAddress((void**)&b2x, g_b2x);
    cudaGetSymbolAddress((void**)&badp, g_bad);
    cudaGetSymbolAddress((void**)&dtm, g_tmaps);

    if (!g_init_done) {
        cudaFuncSetAttribute(gemm_h, cudaFuncAttributeMaxDynamicSharedMemorySize, SMEM_BYTES);
        init_tc(Xh, w13h, w24h, W2h, W1h, Htmp2, HsHe, Th, LsLe, badp, dtm);
        g_init_done = 1;
    }

    // fused prep: small-tensor f2h + bias gather + STREAMING W1 f2h (no transpose)
    f2h_multi<<<512, 256>>>(hidden, sw1, ew1, sw2, ew2, W2w, Xh, w13h, w24h, W2h);
    biascpy<<<3, 256>>>(sb1, eb1, sb2, eb2, b1x, b2x);
    f2h_w1<<<1024, 256>>>(W1, W1h);

    int tc_ok = 0;
    if (g_use_tc) {
        tc_ok = (tc_gemm(3, 4, 2, dtm + 0 * 128, dtm + 1 * 128,
                         Htmp2, BLD, Dd, 1, b1x, Dd, 0, 0, 0, 0) == 0);
        if (!tc_ok) g_use_tc = 0;
    }
    if (tc_ok) {
        tc_gemm(3, 4, 2, dtm + 2 * 128, dtm + 3 * 128,
                HsHe, BLD, Dd, 2, b2x, Dd, 0, 0, 0, 0);
        tc_gemm(1, 4, 2, dtm + 4 * 128, dtm + 5 * 128,
                LsLe, (long long)BLC, Cc, 5, 0, 0, 0, 0, 0, 0);
        // Phase A' (mode 3): U[j',c,d] = sum_e He[j',e] * W1[c,d,e]   (z = c)
        tc_gemm(3, 4, Cc, dtm + 4 * 128, dtm + 6 * 128,
                Th, Dd, (long long)Cc * Dd, 3, 0, 0, 0, 0, 0, 0);
        // Phase B' (mode 4): out rows = i, z = (b,j); per-z vec = Le, per-row = Ls
        tc_gemm(1, 2, BLn, dtm + 4 * 128, dtm + 7 * 128,
                out, 0, 512 * Cc, 4, 0, 0, LsLe + BLC, LsLe, W2b, bs);
    } else {
        const dim3 blk(256);
        gemm_h<<<dim3(6, 8, 1), blk, SMEM_BYTES>>>(Xh, 0, Dd, w13h, 0, Dd, Htmp2, 0, Dd,
                                                   1, sb1, nullptr, nullptr, nullptr, nullptr);
        gemm_h<<<dim3(6, 8, 1), blk, SMEM_BYTES>>>(Htmp2, 0, Dd, w24h, 0, Dd, HsHe, 0, Dd,
                                                   2, sb2, nullptr, nullptr, nullptr, nullptr);
        gemm_h<<<dim3(6, 8, 1), blk, SMEM_BYTES>>>(Xh, 0, Dd, w13h + HD, 0, Dd, Htmp2 + BLD, 0, Dd,
                                                   1, eb1, nullptr, nullptr, nullptr, nullptr);
        gemm_h<<<dim3(6, 8, 1), blk, SMEM_BYTES>>>(Htmp2 + BLD, 0, Dd, w24h + HD, 0, Dd, HsHe + BLD, 0, Dd,
                                                   2, eb2, nullptr, nullptr, nullptr, nullptr);
        gemm_h<<<dim3(2, 8, 1), blk, SMEM_BYTES>>>(HsHe, 0, Dd, W2h, 0, 2 * Dd, LsLe, 0, Cc,
                                                   0, nullptr, nullptr, nullptr, nullptr, nullptr);
        gemm_h<<<dim3(2, 8, 1), blk, SMEM_BYTES>>>(HsHe + BLD, 0, Dd, W2h + Dd, 0, 2 * Dd, LsLe + BLC, 0, Cc,
                                                   0, nullptr, nullptr, nullptr, nullptr, nullptr);
        // Phase A' fallback: U = He x W1h (native), z = c
        gemm_h<<<dim3(6, 8, Cc), blk, SMEM_BYTES>>>(HsHe + BLD, 0, Dd,
                                                    W1h, (long)HD, Dd,
                                                    Th, (long)Dd, (long)Cc * Dd,
                                                    3, nullptr, nullptr, nullptr, nullptr, nullptr);
        // Phase B' fallback: A = Hs, B = U slice, z = (b,j); pass Le as Lsg, Ls as Leg
        gemm_h<<<dim3(2, 4, BLn), blk, SMEM_BYTES>>>(HsHe, 0, Dd, Th, 0, Dd, out, 0, Cc,
                                                     4, nullptr, LsLe + BLC, LsLe, W2b, bs);
    }
}

// round 16
// speedup vs baseline: 1.0613x; 1.0425x over previous
#include <cuda_runtime.h>
#include <cuda_fp16.h>
#include <cstdint>
#include <cstdio>
#include <cstdlib>
#include <cstring>
#include <dlfcn.h>

#define Dd 768
#define Cc 256
#define BLn 1024
#define HD (Dd * Dd)
#define BLD (BLn * Dd)
#define BLC (BLn * Cc)

// Scratch (device globals; zero-initialized)
__device__ __half g_Xh[BLD];
__device__ __half g_w13h[2 * HD];
__device__ __half g_w24h[2 * HD];
__device__ __half g_W2h[Cc * 2 * Dd];
__device__ __half g_W1th[(size_t)Cc * Dd * Dd];   // native W1 f16 [c][d][e]
__device__ __half g_Htmp2[2 * BLD];
__device__ __half g_HsHe[2 * BLD];                // Hs || He
__device__ __half g_Th[(size_t)BLn * Cc * Dd];    // U[j'][c][d]
__device__ float  g_LsLe[2 * BLC];
__device__ float  g_b1x[2 * Dd];
__device__ float  g_b2x[2 * Dd];
__device__ int    g_bad;
__device__ __align__(128) unsigned char g_tmaps[8 * 128];

static __device__ __forceinline__ uint32_t smem_u32(const void* p) {
    uint32_t a;
    asm("{ .reg .u64 t; cvta.to.shared.u64 t, %1; cvt.u32.u64 %0, t; }" : "=r"(a) : "l"(p));
    return a;
}
static __device__ __forceinline__ void cp16(uint32_t dst, const void* src) {
    asm volatile("cp.async.cg.shared.global [%0], [%1], 16;" :: "r"(dst), "l"(src) : "memory");
}
static __device__ __forceinline__ void cp_commit() {
    asm volatile("cp.async.commit_group;" ::: "memory");
}
template <int N>
static __device__ __forceinline__ void cp_wait() {
    asm volatile("cp.async.wait_group %0;" :: "n"(N) : "memory");
}
static __device__ __forceinline__ void mma_f16(float& c0, float& c1, float& c2, float& c3,
                                               uint32_t a0, uint32_t a1, uint32_t a2, uint32_t a3,
                                               uint32_t b0, uint32_t b1) {
    asm volatile(
        "mma.sync.aligned.m16n8k16.row.col.f32.f16.f16.f32 "
        "{%0,%1,%2,%3}, {%4,%5,%6,%7}, {%8,%9}, {%0,%1,%2,%3};"
        : "+f"(c0), "+f"(c1), "+f"(c2), "+f"(c3)
        : "r"(a0), "r"(a1), "r"(a2), "r"(a3), "r"(b0), "r"(b1));
}

// ---------------------------------------------------------------------------
// Legacy fp16 mma.sync GEMM (fallback + validation reference)
// ---------------------------------------------------------------------------
#define ROWH 72
#define ASTG (128 * ROWH)
#define SMEM_BYTES (4 * ASTG * 2 * 2 / 2)

__global__ void __launch_bounds__(256, 2)
gemm_h(const __half* A, long saz, int lda,
       const __half* B, long sbz, int ldb,
       void* Cv, long scz, long ldc,
       int mode, const float* __restrict__ b1,
       const float* __restrict__ Lsg, const float* __restrict__ Leg,
       const float* __restrict__ W2bg, const float* __restrict__ biasg)
{
    extern __shared__ __half smh[];
    __half* As = smh;
    __half* Bs = smh + 2 * ASTG;
    const uint32_t sbase = smem_u32(smh);
    const uint32_t bbase = sbase + 2 * ASTG * 2;

    const int tid = threadIdx.x;
    const int z = blockIdx.z;
    float* Cf = (float*)Cv;
    __half* Ch = (__half*)Cv;
    long ldc_eff = ldc;
    if (mode == 4) {
        A += (long)(z >> 9) * 512 * Dd;
        B += (long)z * Cc * Dd;
        Cf += ((long)(z >> 9) << 26) + (long)(z & 511) * Cc;
        ldc_eff = 512 * Cc;
    } else {
        A += z * saz; B += z * sbz;
        Cf += z * scz; Ch += z * scz;
    }
    const int m0 = blockIdx.y * 128, n0 = blockIdx.x * 128;

    const int pr = tid >> 3, pc = tid & 7;
    const __half* pa0 = A + (long)(m0 + pr) * lda + pc * 8;
    const __half* pb0 = B + (long)(n0 + pr) * ldb + pc * 8;
    const uint32_t qoff = (uint32_t)(pr * ROWH * 2 + pc * 16);
    const uint32_t qa0 = sbase + qoff;
    const uint32_t qb0 = bbase + qoff;
    const uint32_t stgb = ASTG * 2;

    float acc[4][4][4];
#pragma unroll
    for (int mi = 0; mi < 4; mi++)
#pragma unroll
        for (int ni = 0; ni < 4; ni++)
#pragma unroll
            for (int r = 0; r < 4; r++) acc[mi][ni][r] = 0.f;

    const int lane = tid & 31, w = tid >> 5;
    const int g = lane >> 2, tig = lane & 3;
    const int wm = w & 1, wn = w >> 1;

#pragma unroll
    for (int i = 0; i < 4; i++) {
        cp16(qa0 + i * (32 * ROWH * 2), pa0 + (long)(32 * i) * lda);
        cp16(qb0 + i * (32 * ROWH * 2), pb0 + (long)(32 * i) * ldb);
    }
    cp_commit();

    for (int k0 = 0; k0 < 12; k0++) {
        cp_wait<0>();
        __syncthreads();
        if (k0 + 1 < 12) {
            const uint32_t so = ((k0 + 1) & 1) * stgb;
            const long go = (long)(k0 + 1) * 64;
#pragma unroll
            for (int i = 0; i < 4; i++) {
                cp16(qa0 + so + i * (32 * ROWH * 2), pa0 + (long)(32 * i) * lda + go);
                cp16(qb0 + so + i * (32 * ROWH * 2), pb0 + (long)(32 * i) * ldb + go);
            }
            cp_commit();
        }

        const __half* aw = As + (k0 & 1) * ASTG + (wm * 64) * ROWH;
        const __half* bw = Bs + (k0 & 1) * ASTG + (wn * 32) * ROWH;

#pragma unroll
        for (int ks = 0; ks < 4; ks++) {
            const int kh = ks * 16 + 2 * tig;
            uint32_t af[4][4], bf[4][2];
#pragma unroll
            for (int mi = 0; mi < 4; mi++) {
                const __half* p = aw + (mi * 16 + g) * ROWH + kh;
                af[mi][0] = *(const uint32_t*)(p);
                af[mi][1] = *(const uint32_t*)(p + 8 * ROWH);
                af[mi][2] = *(const uint32_t*)(p + 8);
                af[mi][3] = *(const uint32_t*)(p + 8 * ROWH + 8);
            }
#pragma unroll
            for (int ni = 0; ni < 4; ni++) {
                const __half* p = bw + (ni * 8 + g) * ROWH + kh;
                bf[ni][0] = *(const uint32_t*)(p);
                bf[ni][1] = *(const uint32_t*)(p + 8);
            }
#pragma unroll
            for (int mi = 0; mi < 4; mi++)
#pragma unroll
                for (int ni = 0; ni < 4; ni++)
                    mma_f16(acc[mi][ni][0], acc[mi][ni][1], acc[mi][ni][2], acc[mi][ni][3],
                            af[mi][0], af[mi][1], af[mi][2], af[mi][3],
                            bf[ni][0], bf[ni][1]);
        }
    }

    const float* lsr = nullptr; const float* leb = nullptr;
    if (mode == 4) {
        lsr = Lsg + (long)z * Cc;
        leb = Leg + (long)(z >> 9) * 512 * Cc;
    }
#pragma unroll
    for (int mi = 0; mi < 4; mi++) {
#pragma unroll
        for (int ni = 0; ni < 4; ni++) {
            const int col = n0 + wn * 32 + ni * 8 + tig * 2;
#pragma unroll
            for (int h = 0; h < 2; h++) {
                const int row = m0 + wm * 64 + mi * 16 + g + h * 8;
                float x0 = acc[mi][ni][h * 2];
                float x1 = acc[mi][ni][h * 2 + 1];
                if (mode == 1) {
                    x0 = fmaxf(x0 + b1[col], 0.f);
                    x1 = fmaxf(x1 + b1[col + 1], 0.f);
                } else if (mode == 2) {
                    x0 += b1[col]; x1 += b1[col + 1];
                } else if (mode == 4) {
                    const float* ler = leb + (long)row * Cc;
                    x0 += lsr[col] + ler[col] + W2bg[col] + biasg[col];
                    x1 += lsr[col + 1] + ler[col + 1] + W2bg[col + 1] + biasg[col + 1];
                }
                if (mode == 0 || mode == 4) {
                    *(float2*)(Cf + (long)row * ldc_eff + col) = make_float2(x0, x1);
                } else {
                    *(__half2*)(Ch + (long)row * ldc_eff + col) = __floats2half2_rn(x0, x1);
                }
            }
        }
    }
}

// W1 f32 -> f16 native streaming copy
__global__ void __launch_bounds__(256)
f2h_w1(const float* __restrict__ W1, __half* __restrict__ W1h)
{
    const long long n8 = (long long)Cc * HD / 8;
    for (long long i = blockIdx.x * (long long)blockDim.x + threadIdx.x; i < n8;
         i += (long long)gridDim.x * blockDim.x) {
        const float4 a = *(const float4*)(W1 + i * 8);
        const float4 b = *(const float4*)(W1 + i * 8 + 4);
        uint32_t h0, h1, h2, h3;
        asm("{.reg .b16 l,h; cvt.rn.f16.f32 l,%1; cvt.rn.f16.f32 h,%2; mov.b32 %0,{l,h};}"
            : "=r"(h0) : "f"(a.x), "f"(a.y));
        asm("{.reg .b16 l,h; cvt.rn.f16.f32 l,%1; cvt.rn.f16.f32 h,%2; mov.b32 %0,{l,h};}"
            : "=r"(h1) : "f"(a.z), "f"(a.w));
        asm("{.reg .b16 l,h; cvt.rn.f16.f32 l,%1; cvt.rn.f16.f32 h,%2; mov.b32 %0,{l,h};}"
            : "=r"(h2) : "f"(b.x), "f"(b.y));
        asm("{.reg .b16 l,h; cvt.rn.f16.f32 l,%1; cvt.rn.f16.f32 h,%2; mov.b32 %0,{l,h};}"
            : "=r"(h3) : "f"(b.z), "f"(b.w));
        *(uint4*)(W1h + i * 8) = make_uint4(h0, h1, h2, h3);
    }
}

__global__ void f2h_multi(const float* __restrict__ hidden,
                          const float* __restrict__ sw1, const float* __restrict__ ew1,
                          const float* __restrict__ sw2, const float* __restrict__ ew2,
                          const float* __restrict__ W2w,
                          __half* Xh, __half* w13, __half* w24, __half* W2h)
{
    const int total = BLD + 4 * HD + Cc * 2 * Dd;
    for (int i = blockIdx.x * blockDim.x + threadIdx.x; i < total;
         i += gridDim.x * blockDim.x) {
        int j = i;
        if (j < BLD) { Xh[j] = __float2half_rn(hidden[j]); continue; }
        j -= BLD;
        if (j < HD) { w13[j] = __float2half_rn(sw1[j]); continue; }
        j -= HD;
        if (j < HD) { w13[HD + j] = __float2half_rn(ew1[j]); continue; }
        j -= HD;
        if (j < HD) { w24[j] = __float2half_rn(sw2[j]); continue; }
        j -= HD;
        if (j < HD) { w24[HD + j] = __float2half_rn(ew2[j]); continue; }
        j -= HD;
        W2h[j] = __float2half_rn(W2w[j]);
    }
}

__global__ void biascpy(const float* a, const float* b, const float* c, const float* d,
                        float* b1x, float* b2x)
{
    int i = blockIdx.x * blockDim.x + threadIdx.x;
    if (i < Dd) {
        b1x[i] = a[i]; b1x[Dd + i] = b[i];
        b2x[i] = c[i]; b2x[Dd + i] = d[i];
    }
}

__global__ void fillh_k(__half* y, int n, unsigned seed)
{
    for (int i = blockIdx.x * blockDim.x + threadIdx.x; i < n; i += gridDim.x * blockDim.x) {
        unsigned v = (unsigned)i * 2654435761u + seed * 97u;
        y[i] = __float2half_rn((float)((v >> 16) & 1023) / 256.f - 2.f);
    }
}
__global__ void cmp_k(const float* a, const float* b, int n, int* bad)
{
    int i = blockIdx.x * blockDim.x + threadIdx.x;
    if (i < n) {
        float d = fabsf(a[i] - b[i]);
        if (!(d <= 0.25f + 0.01f * fabsf(a[i]))) atomicAdd(bad, 1);
    }
}

// ---------------------------------------------------------------------------
// tcgen05 kernel (NVRTC, sm_103a). Round-16: M=128 tile, 2-stage ring,
// smem 97KB -> TWO CTAs PER SM (two independent pipelines hide each other's
// TMA latency; rounds 12/13 proved single-pipeline overlap can't be fixed).
// A: one box-128 TMA; B: two box-128 TMA (rows n0, n0+128). expect_tx 49152.
// Single 256-col TMEM accumulator, 4 MMA dispatches/chunk, epilogue tid<128.
// ---------------------------------------------------------------------------
static const char* TC_SRC = R"XX(
typedef unsigned int u32; typedef unsigned long long u64; typedef unsigned short u16;
#define MWAIT(a,p) do{ if(alive){ u32 ok=0; for(int t=0;t<4000&&!ok;t++){ \
  asm volatile("{\n\t.reg .pred P;\n\tmbarrier.try_wait.parity.acquire.cta.shared::cta.b64 P, [%1], %2, 0x989680;\n\tselp.b32 %0, 1, 0, P;\n\t}" \
    : "=r"(ok) : "r"(a), "r"(p) : "memory"); } alive = ok; } }while(0)
extern "C" __global__ void __launch_bounds__(288, 2) gtc(
  const void* mA, const void* mB,
  void* Cv, long long scz, long long ldc,
  int mode, const float* b1, long long bstr,
  const float* Lsg, const float* Leg, const float* W2bg, const float* biasg)
{
  extern __shared__ char smem[];
  u32 raw; asm("{ .reg .u64 t; cvta.to.shared.u64 t, %1; cvt.u32.u64 %0, t; }":"=r"(raw):"l"(smem));
  const u32 data = (raw + 1023) & ~(u32)1023;
  const u32 ctrl = data + 98304;
  const u32 bfl[2] = {ctrl, ctrl + 8};
  const u32 bem[2] = {ctrl + 16, ctrl + 24};
  const u32 bdone = ctrl + 32, btm = ctrl + 40;
  const int tid = threadIdx.x, wid = tid >> 5;
  const int z = blockIdx.z;
  u32 alive = 1;
  float* Cf = (float*)Cv; u16* Ch = (u16*)Cv;
  if (mode == 4) Cf += (((long long)(z >> 9)) << 26) + (long long)(z & 511) * 256;
  else { Cf += (long long)z * scz; Ch += (long long)z * scz; }
  const float* b1z = b1 + (long long)z * bstr;
  const int m0 = blockIdx.y * 128, n0 = blockIdx.x * 256;

  int ay = m0, az = 0, bx0 = 0, bz = 0;
  if (mode == 1)      { bz = z; }
  else if (mode == 2) { az = z; bz = z; }
  else if (mode == 5) { ay = m0 + z * 1024; bx0 = z * 768; }
  else if (mode == 3) { ay = 1024 + m0; bz = z; }
  else if (mode == 4) { ay = (z >> 9) * 512 + m0; bz = z; }

  if (tid == 0) {
    asm volatile("mbarrier.init.shared.b64 [%0], 1;"::"r"(bfl[0]):"memory");
    asm volatile("mbarrier.init.shared.b64 [%0], 1;"::"r"(bfl[1]):"memory");
    asm volatile("mbarrier.init.shared.b64 [%0], 1;"::"r"(bem[0]):"memory");
    asm volatile("mbarrier.init.shared.b64 [%0], 1;"::"r"(bem[1]):"memory");
    asm volatile("mbarrier.init.shared.b64 [%0], 1;"::"r"(bdone):"memory");
  }
  if (wid == 8) {
    asm volatile("tcgen05.alloc.cta_group::1.sync.aligned.shared::cta.b32 [%0], 256;"::"r"(btm):"memory");
    asm volatile("tcgen05.relinquish_alloc_permit.cta_group::1.sync.aligned;");
  }
  __syncthreads();
  u32 tmem; asm volatile("ld.shared.b32 %0, [%1];":"=r"(tmem):"r"(btm));

  // stage s at data + s*49152: A 128x128B (16KB), then B 256x128B (32KB)
  if (tid == 0) {
    for (int k = 0; k < 12; k++) {
      const int s = k & 1;
      if (k >= 2) MWAIT(bem[s], ((k >> 1) - 1) & 1);
      const u32 dstA = data + (u32)s * 49152;
      const u32 dstB = dstA + 16384;
      asm volatile("mbarrier.arrive.expect_tx.shared.b64 _, [%0], %1;"
                   :: "r"(bfl[s]), "r"(49152u) : "memory");
      asm volatile("cp.async.bulk.tensor.3d.shared::cta.global.tile.mbarrier::complete_tx::bytes "
                   "[%0], [%1, {%2, %3, %4}], [%5];"
                   :: "r"(dstA), "l"(mA), "r"(k * 64), "r"(ay), "r"(az), "r"(bfl[s]) : "memory");
      asm volatile("cp.async.bulk.tensor.3d.shared::cta.global.tile.mbarrier::complete_tx::bytes "
                   "[%0], [%1, {%2, %3, %4}], [%5];"
                   :: "r"(dstB), "l"(mB), "r"(bx0 + k * 64), "r"(n0), "r"(bz), "r"(bfl[s]) : "memory");
      asm volatile("cp.async.bulk.tensor.3d.shared::cta.global.tile.mbarrier::complete_tx::bytes "
                   "[%0], [%1, {%2, %3, %4}], [%5];"
                   :: "r"(dstB + 16384), "l"(mB), "r"(bx0 + k * 64), "r"(n0 + 128), "r"(bz), "r"(bfl[s]) : "memory");
    }
  } else if (wid == 8 && (tid & 31) == 0) {
    const u64 base = (2ULL << 61) | (1ULL << 46) | (64ULL << 32) | (1ULL << 16);
    const u64 d0 = base | ((data >> 4) & 0x3FFF);
    const u32 idesc = (1u << 4) | (32u << 17) | (8u << 24);
    for (int k = 0; k < 12; k++) {
      const int s = k & 1;
      MWAIT(bfl[s], (k >> 1) & 1);
      u64 dstage = d0 + (u64)s * 3072;   // 49152 / 16
      u64 dA = dstage, dB = dstage + 1024;
      #pragma unroll
      for (int i = 0; i < 4; i++) {
        u32 en = (u32)(k | i);
        asm volatile("{\n\t.reg .pred p;\n\tsetp.ne.u32 p, %4, 0;\n\t"
          "tcgen05.mma.cta_group::1.kind::f16 [%0], %1, %2, %3, {%5,%5,%5,%5}, p;\n\t}"
          ::"r"(tmem),"l"(dA + 2*i),"l"(dB + 2*i),"r"(idesc),"r"(en),"r"(0u):"memory");
      }
      asm volatile("tcgen05.commit.cta_group::1.mbarrier::arrive::one.shared::cluster.b64 [%0];"::"r"(bem[s]):"memory");
    }
    asm volatile("tcgen05.commit.cta_group::1.mbarrier::arrive::one.shared::cluster.b64 [%0];"::"r"(bdone):"memory");
  }

  MWAIT(bdone, 0);
  asm volatile("tcgen05.fence::after_thread_sync;":::"memory");

  if (tid < 128) {
    const long long row = m0 + tid;
    const float* lsr = 0; const float* ler = 0;
    if (mode == 4) {
      lsr = Lsg + (long long)z * 256;
      ler = Leg + ((long long)(z >> 9) * 512 + row) * 256;
    }
    for (int nc = 0; nc < 8; nc++) {
      u32 r[32];
      asm volatile("tcgen05.ld.sync.aligned.32x32b.x32.b32 "
        "{%0,%1,%2,%3,%4,%5,%6,%7,%8,%9,%10,%11,%12,%13,%14,%15,"
        "%16,%17,%18,%19,%20,%21,%22,%23,%24,%25,%26,%27,%28,%29,%30,%31}, [%32];"
        : "=r"(r[0]),"=r"(r[1]),"=r"(r[2]),"=r"(r[3]),"=r"(r[4]),"=r"(r[5]),"=r"(r[6]),"=r"(r[7]),
          "=r"(r[8]),"=r"(r[9]),"=r"(r[10]),"=r"(r[11]),"=r"(r[12]),"=r"(r[13]),"=r"(r[14]),"=r"(r[15]),
          "=r"(r[16]),"=r"(r[17]),"=r"(r[18]),"=r"(r[19]),"=r"(r[20]),"=r"(r[21]),"=r"(r[22]),"=r"(r[23]),
          "=r"(r[24]),"=r"(r[25]),"=r"(r[26]),"=r"(r[27]),"=r"(r[28]),"=r"(r[29]),"=r"(r[30]),"=r"(r[31])
        : "r"(tmem + nc * 32));
      asm volatile("tcgen05.wait::ld.sync.aligned;":::"memory");
      const int nb = n0 + nc * 32;
      float v[32];
      #pragma unroll
      for (int c = 0; c < 32; c++) {
        float x; asm("mov.b32 %0, %1;" : "=f"(x) : "r"(r[c]));
        const int n = nb + c;
        if (mode == 1)      { x = x + b1z[n]; x = x > 0.f ? x : 0.f; }
        else if (mode == 2) x = x + b1z[n];
        else if (mode == 4) x += lsr[n] + ler[n] + W2bg[n] + biasg[n];
        v[c] = x;
      }
      if (mode == 0 || mode == 4 || mode == 5) {
        float* dst = Cf + row * ldc + nb;
        #pragma unroll
        for (int j = 0; j < 8; j++)
          asm volatile("st.global.v4.f32 [%0], {%1,%2,%3,%4};"
            ::"l"(dst + 4*j),"f"(v[4*j]),"f"(v[4*j+1]),"f"(v[4*j+2]),"f"(v[4*j+3]):"memory");
      } else {
        u16* dst = Ch + row * ldc + nb;
        u32 hp[16];
        #pragma unroll
        for (int j = 0; j < 16; j++) {
          asm("{\n\t.reg .b16 lo, hi;\n\tcvt.rn.f16.f32 lo, %1;\n\tcvt.rn.f16.f32 hi, %2;\n\t"
              "mov.b32 %0, {lo, hi};\n\t}" : "=r"(hp[j]) : "f"(v[2*j]), "f"(v[2*j+1]));
        }
        #pragma unroll
        for (int j = 0; j < 4; j++)
          asm volatile("st.global.v4.b32 [%0], {%1,%2,%3,%4};"
            ::"l"(dst + 8*j),"r"(hp[4*j]),"r"(hp[4*j+1]),"r"(hp[4*j+2]),"r"(hp[4*j+3]):"memory");
      }
    }
  }
  __syncthreads();
  if (wid == 8)
    asm volatile("tcgen05.dealloc.cta_group::1.sync.aligned.b32 %0, 256;"::"r"(tmem));
}
)XX";

// ---------------------------------------------------------------------------
// Runtime JIT plumbing
// ---------------------------------------------------------------------------
#define TC_SMEM 99392   // 2 stages * 49152 + ctrl + align slack -> 2 CTAs/SM

#if defined(CUDA_API_PER_THREAD_DEFAULT_STREAM) || defined(__CUDA_API_PER_THREAD_DEFAULT_STREAM__)
#define HS ((void*)0x2)
#else
#define HS ((void*)0x1)
#endif

typedef int (*nvrtcCreate_t)(void**, const char*, const char*, int, const char* const*, const char* const*);
typedef int (*nvrtcCompile_t)(void*, int, const char* const*);
typedef int (*nvrtcGetSize_t)(void*, size_t*);
typedef int (*nvrtcGetData_t)(void*, char*);
typedef int (*cuModLoad_t)(void**, const void*);
typedef int (*cuModGetFn_t)(void**, void*, const char*);
typedef int (*cuFnSetAttr_t)(void*, int, int);
typedef int (*cuLaunch_t)(void*, unsigned, unsigned, unsigned, unsigned, unsigned, unsigned,
                          unsigned, void*, void**, void**);
typedef int (*cuTMEnc_t)(void*, int, unsigned, void*, const uint64_t*, const uint64_t*,
                         const uint32_t*, const uint32_t*, int, int, int, int);

static int g_init_done = 0;
static int g_use_tc = 0;
static void* g_fn = nullptr;
static cuLaunch_t p_launch = nullptr;

static int tc_gemm(int gx, int gy, int gz,
                   const void* mA, const void* mB,
                   void* C, long long scz, long long ldc, int mode,
                   const void* b1, long long bstr,
                   const void* Ls, const void* Le,
                   const void* W2b, const void* bias)
{
    void* args[12] = {(void*)&mA, (void*)&mB, (void*)&C, (void*)&scz, (void*)&ldc,
                      (void*)&mode, (void*)&b1, (void*)&bstr,
                      (void*)&Ls, (void*)&Le, (void*)&W2b, (void*)&bias};
    return p_launch(g_fn, gx, gy, gz, 288, 1, 1, TC_SMEM, HS, args, 0);
}

static void* try_dlopen(const char* const* names, int n) {
    for (int i = 0; i < n; i++) {
        void* h = dlopen(names[i], RTLD_NOW | RTLD_GLOBAL);
        if (h) return h;
    }
    return nullptr;
}

static int enc3(cuTMEnc_t f, void* map, void* addr,
                uint64_t d0, uint64_t d1, uint64_t d2,
                uint64_t s1b, uint64_t s2b)
{
    uint64_t dims[3] = {d0, d1, d2};
    uint64_t str[2] = {s1b, s2b};
    uint32_t box[3] = {64, 128, 1};      // 128-row boxes (M=128 tiles)
    uint32_t es[3] = {1, 1, 1};
    return f(map, 6, 3, addr, dims, str, box, es, 0, 3, 2, 0);
}

static void init_tc(__half* Xh, __half* w13h, __half* w24h, __half* W2h,
                    __half* W1h, __half* Htmp2, __half* HsHe, __half* Th,
                    float* LsLe, int* badp, unsigned char* dtm)
{
    const char* nvrtc_names[] = {"libnvrtc.so", "libnvrtc.so.13", "libnvrtc.so.12",
                                 "/usr/local/cuda/lib64/libnvrtc.so"};
    const char* cuda_names[] = {"libcuda.so.1", "libcuda.so"};
    void* hn = try_dlopen(nvrtc_names, 4);
    void* hc = try_dlopen(cuda_names, 2);
    if (!hn || !hc) { fprintf(stderr, "tcjit: dlopen failed\n"); return; }

    auto nCreate = (nvrtcCreate_t)dlsym(hn, "nvrtcCreateProgram");
    auto nCompile = (nvrtcCompile_t)dlsym(hn, "nvrtcCompileProgram");
    auto nCubSz = (nvrtcGetSize_t)dlsym(hn, "nvrtcGetCUBINSize");
    auto nCub = (nvrtcGetData_t)dlsym(hn, "nvrtcGetCUBIN");
    auto nLogSz = (nvrtcGetSize_t)dlsym(hn, "nvrtcGetProgramLogSize");
    auto nLog = (nvrtcGetData_t)dlsym(hn, "nvrtcGetProgramLog");
    auto mLoad = (cuModLoad_t)dlsym(hc, "cuModuleLoadData");
    auto mGetFn = (cuModGetFn_t)dlsym(hc, "cuModuleGetFunction");
    auto fAttr = (cuFnSetAttr_t)dlsym(hc, "cuFuncSetAttribute");
    auto tmEnc = (cuTMEnc_t)dlsym(hc, "cuTensorMapEncodeTiled");
    p_launch = (cuLaunch_t)dlsym(hc, "cuLaunchKernel");
    if (!nCreate || !nCompile || !nCubSz || !nCub || !mLoad || !mGetFn || !fAttr ||
        !p_launch || !tmEnc) {
        fprintf(stderr, "tcjit: dlsym failed\n"); return;
    }

    void* prog = nullptr;
    if (nCreate(&prog, TC_SRC, "tc.cu", 0, nullptr, nullptr)) {
        fprintf(stderr, "tcjit: create failed\n"); return;
    }
    const char* opts1[] = {"--gpu-architecture=sm_103a", "--std=c++14"};
    int cres = nCompile(prog, 2, opts1);
    if (cres) {
        if (nLogSz && nLog) {
            size_t ls = 0; nLogSz(prog, &ls);
            if (ls > 1) { char* lg = (char*)malloc(ls + 1); nLog(prog, lg); lg[ls] = 0;
                          fprintf(stderr, "tcjit: compile log:\n%s\n", lg); free(lg); }
        }
        fprintf(stderr, "tcjit: compile failed (%d)\n", cres);
        return;
    }
    size_t csz = 0;
    if (nCubSz(prog, &csz) || csz == 0) { fprintf(stderr, "tcjit: cubin size fail\n"); return; }
    char* cub = (char*)malloc(csz);
    nCub(prog, cub);
    void* mod = nullptr;
    int lr = mLoad(&mod, cub);
    free(cub);
    if (lr) { fprintf(stderr, "tcjit: module load failed %d\n", lr); return; }
    if (mGetFn(&g_fn, mod, "gtc")) { fprintf(stderr, "tcjit: getfn failed\n"); return; }
    fAttr(g_fn, 8, TC_SMEM);

    static unsigned char hmaps[8 * 128] __attribute__((aligned(64)));
    memset(hmaps, 0, sizeof(hmaps));
    int e = 0;
    e |= enc3(tmEnc, hmaps + 0 * 128, Xh,    768, 1024, 1,    1536, (uint64_t)BLD * 2);
    e |= enc3(tmEnc, hmaps + 1 * 128, w13h,  768, 768,  2,    1536, (uint64_t)HD * 2);
    e |= enc3(tmEnc, hmaps + 2 * 128, Htmp2, 768, 1024, 2,    1536, (uint64_t)BLD * 2);
    e |= enc3(tmEnc, hmaps + 3 * 128, w24h,  768, 768,  2,    1536, (uint64_t)HD * 2);
    e |= enc3(tmEnc, hmaps + 4 * 128, HsHe,  768, 2048, 1,    1536, (uint64_t)2 * BLD * 2);
    e |= enc3(tmEnc, hmaps + 5 * 128, W2h,   1536, 256, 1,    3072, (uint64_t)Cc * 2 * Dd * 2);
    e |= enc3(tmEnc, hmaps + 6 * 128, W1h,   768, 768,  256,  1536, (uint64_t)HD * 2);
    e |= enc3(tmEnc, hmaps + 7 * 128, Th,    768, 256,  1024, 1536, (uint64_t)Cc * Dd * 2);
    if (e) { fprintf(stderr, "tcjit: tensormap encode failed %d\n", e); return; }
    cudaMemcpy(dtm, hmaps, sizeof(hmaps), cudaMemcpyHostToDevice);

    // ---- validation + diagnostic ----
    fillh_k<<<192, 256>>>(Xh, BLD, 1u);
    fillh_k<<<192, 256>>>(w13h, HD, 7u);
    gemm_h<<<dim3(2, 2, 1), 256, SMEM_BYTES>>>(Xh, 0, Dd, w13h, 0, Dd, (void*)LsLe, 0, Cc,
                                               0, nullptr, nullptr, nullptr, nullptr, nullptr);
    // DIAGNOSTIC: phase-A'-shaped launch for the ncu capture slot
    int dres = tc_gemm(3, 8, Cc, dtm + 4 * 128, dtm + 6 * 128,
                       Th, Dd, (long long)Cc * Dd, 3, 0, 0, 0, 0, 0, 0);
    if (dres) { fprintf(stderr, "tcjit: diag launch failed %d\n", dres); return; }
    // validation: 256 rows via gy=2
    int lres = tc_gemm(1, 2, 1, dtm + 0 * 128, dtm + 1 * 128,
                       LsLe + BLC, 0, Cc, 0, 0, 0, 0, 0, 0, 0);
    if (lres) { fprintf(stderr, "tcjit: launch failed %d\n", lres); return; }
    cudaMemset(badp, 0, sizeof(int));
    cmp_k<<<256, 256>>>(LsLe, LsLe + BLC, 256 * Cc, badp);
    cudaError_t serr = cudaDeviceSynchronize();
    if (serr != cudaSuccess) {
        fprintf(stderr, "tcjit: validation sync error: %s\n", cudaGetErrorString(serr));
        return;
    }
    int bad = 1 << 30;
    cudaMemcpy(&bad, badp, sizeof(int), cudaMemcpyDeviceToHost);
    fprintf(stderr, "tcjit: validation mismatches = %d / %d\n", bad, 256 * Cc);
    if (bad == 0) g_use_tc = 1;
}

extern "C" void kernel_launch(void* const* d_in, const int* in_sizes, int n_in,
                              void* d_out, int out_size)
{
    const float* hidden = (const float*)d_in[0];
    const float* sw1 = (const float*)d_in[1];
    const float* sb1 = (const float*)d_in[2];
    const float* sw2 = (const float*)d_in[3];
    const float* sb2 = (const float*)d_in[4];
    const float* ew1 = (const float*)d_in[5];
    const float* eb1 = (const float*)d_in[6];
    const float* ew2 = (const float*)d_in[7];
    const float* eb2 = (const float*)d_in[8];
    const float* W1  = (const float*)d_in[9];
    const float* W2w = (const float*)d_in[10];
    const float* W2b = (const float*)d_in[11];
    const float* bs  = (const float*)d_in[12];
    float* out = (float*)d_out;

    __half *Xh, *w13h, *w24h, *W2h, *W1h, *Htmp2, *HsHe, *Th;
    float *LsLe, *b1x, *b2x;
    int* badp;
    unsigned char* dtm;
    cudaGetSymbolAddress((void**)&Xh, g_Xh);
    cudaGetSymbolAddress((void**)&w13h, g_w13h);
    cudaGetSymbolAddress((void**)&w24h, g_w24h);
    cudaGetSymbolAddress((void**)&W2h, g_W2h);
    cudaGetSymbolAddress((void**)&W1h, g_W1th);
    cudaGetSymbolAddress((void**)&Htmp2, g_Htmp2);
    cudaGetSymbolAddress((void**)&HsHe, g_HsHe);
    cudaGetSymbolAddress((void**)&Th, g_Th);
    cudaGetSymbolAddress((void**)&LsLe, g_LsLe);
    cudaGetSymbolAddress((void**)&b1x, g_b1x);
    cudaGetSymbolAddress((void**)&b2x, g_b2x);
    cudaGetSymbolAddress((void**)&badp, g_bad);
    cudaGetSymbolAddress((void**)&dtm, g_tmaps);

    if (!g_init_done) {
        cudaFuncSetAttribute(gemm_h, cudaFuncAttributeMaxDynamicSharedMemorySize, SMEM_BYTES);
        init_tc(Xh, w13h, w24h, W2h, W1h, Htmp2, HsHe, Th, LsLe, badp, dtm);
        g_init_done = 1;
    }

    // fused prep
    f2h_multi<<<512, 256>>>(hidden, sw1, ew1, sw2, ew2, W2w, Xh, w13h, w24h, W2h);
    biascpy<<<3, 256>>>(sb1, eb1, sb2, eb2, b1x, b2x);
    f2h_w1<<<1024, 256>>>(W1, W1h);

    int tc_ok = 0;
    if (g_use_tc) {
        // MLP layer 1, s+e batched: grid (3, 8, 2)
        tc_ok = (tc_gemm(3, 8, 2, dtm + 0 * 128, dtm + 1 * 128,
                         Htmp2, BLD, Dd, 1, b1x, Dd, 0, 0, 0, 0) == 0);
        if (!tc_ok) g_use_tc = 0;
    }
    if (tc_ok) {
        tc_gemm(3, 8, 2, dtm + 2 * 128, dtm + 3 * 128,
                HsHe, BLD, Dd, 2, b2x, Dd, 0, 0, 0, 0);
        tc_gemm(1, 8, 2, dtm + 4 * 128, dtm + 5 * 128,
                LsLe, (long long)BLC, Cc, 5, 0, 0, 0, 0, 0, 0);
        // Phase A': U[j',c,d] = sum_e He[j',e] * W1[c,d,e]   (z = c)
        tc_gemm(3, 8, Cc, dtm + 4 * 128, dtm + 6 * 128,
                Th, Dd, (long long)Cc * Dd, 3, 0, 0, 0, 0, 0, 0);
        // Phase B': out rows = i, z = (b,j); per-z vec = Le, per-row = Ls
        tc_gemm(1, 4, BLn, dtm + 4 * 128, dtm + 7 * 128,
                out, 0, 512 * Cc, 4, 0, 0, LsLe + BLC, LsLe, W2b, bs);
    } else {
        const dim3 blk(256);
        gemm_h<<<dim3(6, 8, 1), blk, SMEM_BYTES>>>(Xh, 0, Dd, w13h, 0, Dd, Htmp2, 0, Dd,
                                                   1, sb1, nullptr, nullptr, nullptr, nullptr);
        gemm_h<<<dim3(6, 8, 1), blk, SMEM_BYTES>>>(Htmp2, 0, Dd, w24h, 0, Dd, HsHe, 0, Dd,
                                                   2, sb2, nullptr, nullptr, nullptr, nullptr);
        gemm_h<<<dim3(6, 8, 1), blk, SMEM_BYTES>>>(Xh, 0, Dd, w13h + HD, 0, Dd, Htmp2 + BLD, 0, Dd,
                                                   1, eb1, nullptr, nullptr, nullptr, nullptr);
        gemm_h<<<dim3(6, 8, 1), blk, SMEM_BYTES>>>(Htmp2 + BLD, 0, Dd, w24h + HD, 0, Dd, HsHe + BLD, 0, Dd,
                                                   2, eb2, nullptr, nullptr, nullptr, nullptr);
        gemm_h<<<dim3(2, 8, 1), blk, SMEM_BYTES>>>(HsHe, 0, Dd, W2h, 0, 2 * Dd, LsLe, 0, Cc,
                                                   0, nullptr, nullptr, nullptr, nullptr, nullptr);
        gemm_h<<<dim3(2, 8, 1), blk, SMEM_BYTES>>>(HsHe + BLD, 0, Dd, W2h + Dd, 0, 2 * Dd, LsLe + BLC, 0, Cc,
                                                   0, nullptr, nullptr, nullptr, nullptr, nullptr);
        gemm_h<<<dim3(6, 8, Cc), blk, SMEM_BYTES>>>(HsHe + BLD, 0, Dd,
                                                    W1h, (long)HD, Dd,
                                                    Th, (long)Dd, (long)Cc * Dd,
                                                    3, nullptr, nullptr, nullptr, nullptr, nullptr);
        gemm_h<<<dim3(2, 4, BLn), blk, SMEM_BYTES>>>(HsHe, 0, Dd, Th, 0, Dd, out, 0, Cc,
                                                     4, nullptr, LsLe + BLC, LsLe, W2b, bs);
    }
}